// round 10
// baseline (speedup 1.0000x reference)
#include <cuda_runtime.h>
#include <math.h>

#define RPB 128      // rows per tile
#define TPB 512      // threads per block (16 warps)
#define WSTRIDE 132  // padded stride (floats): conflict-free frag loads

// Shared layout (floats):
#define OFF_W2   0                         // [128][132] = 16896 (tf32 bits, resident)
#define OFF_Z1   (OFF_W2  + 128*WSTRIDE)   // [128][132] = 16896 (staging overlay rows<36)
#define OFF_H1   (OFF_Z1  + 128*WSTRIDE)   // [128][12]  = 1536
#define OFF_SE   (OFF_H1  + 1536)          // [128][18]  = 2304
#define OFF_DV   (OFF_SE  + 2304)          // [128][6]   = 768
#define OFF_WC   (OFF_DV  + 768)           // [12][40]   = 480 (Wih|Whh fused, zero-padded)
#define SMEM_FLOATS (OFF_WC + 480 + 16)
#define SMEM_BYTES  (SMEM_FLOATS * 4)      // ~155.6 KB -> 1 CTA/SM

// staging offsets inside the Z1 region (consumed only by phase 1)
#define STG_S  (OFF_Z1)          // [128][18] = 576 float4
#define STG_A  (OFF_Z1 + 2304)   // [128][6]  = 192 float4
#define STG_H0 (OFF_Z1 + 3072)   // [128][12] = 384 float4

__device__ __forceinline__ float lrelu(float z) { return z >= 0.0f ? z : 0.1f * z; }

__device__ __forceinline__ float fast_tanh(float x) {
    float e = __expf(2.0f * x);
    return 1.0f - __fdividef(2.0f, e + 1.0f);
}

__device__ __forceinline__ unsigned f2tf(float f) {
    unsigned u;
    asm("cvt.rna.tf32.f32 %0, %1;" : "=r"(u) : "f"(f));
    return u;
}

__device__ __forceinline__ unsigned long long ffma2(unsigned long long a,
                                                    unsigned long long b,
                                                    unsigned long long c) {
    unsigned long long d;
    asm("fma.rn.f32x2 %0, %1, %2, %3;" : "=l"(d) : "l"(a), "l"(b), "l"(c));
    return d;
}
__device__ __forceinline__ float unpack_sum(unsigned long long u) {
    float2 f;
    asm("mov.b64 {%0, %1}, %2;" : "=f"(f.x), "=f"(f.y) : "l"(u));
    return f.x + f.y;
}
__device__ __forceinline__ unsigned long long pack2(float lo, float hi) {
    unsigned long long r;
    asm("mov.b64 %0, {%1, %2};" : "=l"(r) : "f"(lo), "f"(hi));
    return r;
}

__device__ __forceinline__ void mma_tf32(float* c, const unsigned* a, const unsigned* b) {
    asm volatile(
        "mma.sync.aligned.m16n8k8.row.col.f32.tf32.tf32.f32 "
        "{%0,%1,%2,%3}, {%4,%5,%6,%7}, {%8,%9}, {%0,%1,%2,%3};"
        : "+f"(c[0]), "+f"(c[1]), "+f"(c[2]), "+f"(c[3])
        : "r"(a[0]), "r"(a[1]), "r"(a[2]), "r"(a[3]), "r"(b[0]), "r"(b[1]));
}

__global__ __launch_bounds__(TPB, 1)
void auv_step_kernel(const float* __restrict__ s,
                     const float* __restrict__ a,
                     const float* __restrict__ h0,
                     const float* __restrict__ Wih,
                     const float* __restrict__ Whh,
                     const float* __restrict__ W1,
                     const float* __restrict__ W2,
                     const float* __restrict__ W3,
                     float* __restrict__ out,
                     int Krows, int ntiles)
{
    extern __shared__ float sm[];
    float* sW2  = sm + OFF_W2;
    float* sZ1  = sm + OFF_Z1;
    float* sH1  = sm + OFF_H1;
    float* sSE  = sm + OFF_SE;
    float* sDV  = sm + OFF_DV;
    float* sWC  = sm + OFF_WC;

    const int tid = threadIdx.x;
    const long long Kll = (long long)Krows;

    // ---- one-time staging: W2 -> tf32 smem; fused RNN weight table ----
    {
        const float4* W2v = (const float4*)W2;
        #pragma unroll
        for (int i = tid; i < 4096; i += TPB) {
            float4 v = W2v[i];
            uint4 t;
            t.x = f2tf(v.x); t.y = f2tf(v.y); t.z = f2tf(v.z); t.w = f2tf(v.w);
            const int row = i >> 5, c4 = i & 31;
            *(uint4*)(sW2 + row * WSTRIDE + c4 * 4) = t;
        }
        // sWC[j][k] = Wih[j][k] (k<21) | Whh[j][k-21] (21<=k<33) | 0
        if (tid < 480) {
            const int j = tid / 40, k = tid - j * 40;
            float v = 0.0f;
            if (k < 21) v = Wih[j * 21 + k];
            else if (k < 33) v = Whh[j * 12 + (k - 21)];
            sWC[tid] = v;
        }
    }

    // ---- stage first tile directly ----
    {
        const long long rb0 = (long long)blockIdx.x * RPB;
        const float4* sv = (const float4*)(s  + rb0 * 18);
        const float4* av = (const float4*)(a  + rb0 * 6);
        const float4* hv = (const float4*)(h0 + rb0 * 12);
        for (int i = tid; i < 576; i += TPB) ((float4*)(sm + STG_S))[i] = sv[i];
        if (tid < 192) ((float4*)(sm + STG_A))[tid]  = av[tid];
        if (tid < 384) ((float4*)(sm + STG_H0))[tid] = hv[tid];
    }

    for (int tile = blockIdx.x; tile < ntiles; tile += gridDim.x) {
        const long long rowBase = (long long)tile * RPB;
        __syncthreads();   // staging (initial or from prev iteration) visible

        // ---- phase 1: tid<128 -> SE(3); tid 128..511 -> RNN (3 thr/row, 4 outs) ----
        if (tid < RPB) {
            const int r = tid;
            const long long g = rowBase + r;
            const float* Sr = sm + STG_S + r * 18;

            const float p0 = Sr[0], p1 = Sr[1], p2 = Sr[2];
            float R[9];
            #pragma unroll
            for (int i = 0; i < 9; i++) R[i] = Sr[3 + i];
            float v[6];
            #pragma unroll
            for (int i = 0; i < 6; i++) v[i] = Sr[12 + i];

            const float DT = 0.1f;
            const float rho0 = v[0] * DT, rho1 = v[1] * DT, rho2 = v[2] * DT;
            const float px = v[3] * DT, py = v[4] * DT, pz = v[5] * DT;
            const float th2 = px * px + py * py + pz * pz;
            const bool small = th2 < 1e-8f;
            const float th2s = small ? 1.0f : th2;
            const float th = sqrtf(th2s);
            const float sth = __sinf(th), cth = __cosf(th);
            const float A = small ? (1.0f - th2 * (1.0f / 6.0f))  : __fdividef(sth, th);
            const float B = small ? (0.5f - th2 * (1.0f / 24.0f)) : __fdividef(1.0f - cth, th2s);
            const float C = small ? (1.0f / 6.0f - th2 * (1.0f / 120.0f))
                                  : __fdividef(th - sth, th2s * th);

            const float S[9]  = {0.0f, -pz, py,  pz, 0.0f, -px,  -py, px, 0.0f};
            float S2[9];
            S2[0] = -(py * py + pz * pz); S2[1] = px * py;              S2[2] = px * pz;
            S2[3] = px * py;              S2[4] = -(px * px + pz * pz); S2[5] = py * pz;
            S2[6] = px * pz;              S2[7] = py * pz;              S2[8] = -(px * px + py * py);

            float Re[9], Vm[9];
            #pragma unroll
            for (int i = 0; i < 9; i++) {
                const float I = (i == 0 || i == 4 || i == 8) ? 1.0f : 0.0f;
                Re[i] = I + A * S[i] + B * S2[i];
                Vm[i] = I + B * S[i] + C * S2[i];
            }
            const float pe0 = Vm[0] * rho0 + Vm[1] * rho1 + Vm[2] * rho2;
            const float pe1 = Vm[3] * rho0 + Vm[4] * rho1 + Vm[5] * rho2;
            const float pe2 = Vm[6] * rho0 + Vm[7] * rho1 + Vm[8] * rho2;

            float Rn[9];
            #pragma unroll
            for (int i = 0; i < 3; i++)
                #pragma unroll
                for (int j = 0; j < 3; j++)
                    Rn[i * 3 + j] = R[i * 3 + 0] * Re[0 + j] + R[i * 3 + 1] * Re[3 + j] + R[i * 3 + 2] * Re[6 + j];

            const float pn0 = R[0] * pe0 + R[1] * pe1 + R[2] * pe2 + p0;
            const float pn1 = R[3] * pe0 + R[4] * pe1 + R[5] * pe2 + p1;
            const float pn2 = R[6] * pe0 + R[7] * pe1 + R[8] * pe2 + p2;

            float Ri[9] = {Rn[0], Rn[3], Rn[6], Rn[1], Rn[4], Rn[7], Rn[2], Rn[5], Rn[8]};
            const float pi0 = -(Ri[0] * pn0 + Ri[1] * pn1 + Ri[2] * pn2);
            const float pi1 = -(Ri[3] * pn0 + Ri[4] * pn1 + Ri[5] * pn2);
            const float pi2 = -(Ri[6] * pn0 + Ri[7] * pn1 + Ri[8] * pn2);

            const float u0 = R[0] * v[0] + R[1] * v[1] + R[2] * v[2];
            const float u1 = R[3] * v[0] + R[4] * v[1] + R[5] * v[2];
            const float u2 = R[6] * v[0] + R[7] * v[1] + R[8] * v[2];
            const float w0 = R[0] * v[3] + R[1] * v[4] + R[2] * v[5];
            const float w1 = R[3] * v[3] + R[4] * v[4] + R[5] * v[5];
            const float w2 = R[6] * v[3] + R[7] * v[4] + R[8] * v[5];
            const float t0 = u0 + (p1 * w2 - p2 * w1);
            const float t1 = u1 + (p2 * w0 - p0 * w2);
            const float t2 = u2 + (p0 * w1 - p1 * w0);

            float* se = sSE + r * 18;
            #pragma unroll
            for (int i = 0; i < 9; i++) se[i] = Ri[i];
            se[9]  = pi0; se[10] = pi1; se[11] = pi2;
            se[12] = t0;  se[13] = t1;  se[14] = t2;
            se[15] = w0;  se[16] = w1;  se[17] = w2;

            float* o = out + g * 18;
            o[0] = pn0; o[1] = pn1; o[2] = pn2;
            #pragma unroll
            for (int i = 0; i < 9; i++) o[3 + i] = Rn[i];
        } else {
            const int idx = tid - RPB;            // 0..383
            const int r  = idx / 3;               // row 0..127
            const int j0 = (idx - r * 3) * 4;     // output group: 0,4,8
            const float* Sr  = sm + STG_S  + r * 18;
            const float* Ar  = sm + STG_A  + r * 6;
            const float* H0r = sm + STG_H0 + r * 12;

            // x[0..14]=s[3..17], x[15..20]=a, x[21..32]=h0, x[33..39]=0; packed f32x2
            float x[40];
            #pragma unroll
            for (int i = 0; i < 15; i++) x[i] = Sr[3 + i];
            #pragma unroll
            for (int i = 0; i < 6; i++) x[15 + i] = Ar[i];
            #pragma unroll
            for (int i = 0; i < 12; i++) x[21 + i] = H0r[i];
            #pragma unroll
            for (int i = 33; i < 40; i++) x[i] = 0.0f;
            unsigned long long xp[20];
            #pragma unroll
            for (int i = 0; i < 20; i++) xp[i] = pack2(x[2 * i], x[2 * i + 1]);

            float h4[4];
            #pragma unroll
            for (int jj = 0; jj < 4; jj++) {
                const unsigned long long* wp =
                    (const unsigned long long*)(sWC + (j0 + jj) * 40);
                unsigned long long acc = 0ull;
                #pragma unroll
                for (int q = 0; q < 20; q++) acc = ffma2(xp[q], wp[q], acc);
                h4[jj] = fast_tanh(unpack_sum(acc));
            }
            // (r*12 + j0)*4B = r*48 + j0*16 -> 16B aligned
            *(float4*)(sH1 + r * 12 + j0) = make_float4(h4[0], h4[1], h4[2], h4[3]);
        }
        __syncthreads();

        // ---- phase 2: z1 (2 cols x 16 rows/thread) ; prefetch next ; zero sDV ----
        const int tile2 = tile + gridDim.x;
        const bool hasNext = tile2 < ntiles;
        float4 pf0a = make_float4(0.f, 0.f, 0.f, 0.f);
        float4 pf0b = pf0a, pf1 = pf0a, pf2 = pf0a;
        {
            if (hasNext) {
                const long long rb2 = (long long)tile2 * RPB;
                const float4* sv = (const float4*)(s + rb2 * 18);
                pf0a = __ldg(sv + tid);                             // 0..511
                if (tid < 64)  pf0b = __ldg(sv + 512 + tid);        // 512..575
                if (tid < 192) pf1 = __ldg((const float4*)(a  + rb2 * 6)  + tid);
                if (tid < 384) pf2 = __ldg((const float4*)(h0 + rb2 * 12) + tid);
            }
            if (tid < 192) ((float4*)sDV)[tid] = make_float4(0.f, 0.f, 0.f, 0.f);

            const int c0 = (tid & 63) * 2;        // even col
            const int rs = tid >> 6;              // 0..7
            const float4* wa4 = (const float4*)(W1 + c0 * 12);        // cols c0, c0+1: 6 float4
            float4 wv[6];
            #pragma unroll
            for (int q = 0; q < 6; q++) wv[q] = __ldg(wa4 + q);
            unsigned long long w[12];
            #pragma unroll
            for (int q = 0; q < 6; q++) {
                w[2 * q]     = *(unsigned long long*)&wv[q].x;
                w[2 * q + 1] = *(unsigned long long*)&wv[q].z;
            }
            #pragma unroll
            for (int r = rs; r < RPB; r += 8) {
                const unsigned long long* hp = (const unsigned long long*)(sH1 + r * 12);
                unsigned long long h6[6];
                #pragma unroll
                for (int q = 0; q < 6; q++) h6[q] = hp[q];
                unsigned long long a0 = 0ull, a1 = 0ull;
                #pragma unroll
                for (int q = 0; q < 6; q++) {
                    a0 = ffma2(h6[q], w[q], a0);
                    a1 = ffma2(h6[q], w[6 + q], a1);
                }
                const unsigned long long z2 =
                    pack2(__uint_as_float(f2tf(lrelu(unpack_sum(a0)))),
                          __uint_as_float(f2tf(lrelu(unpack_sum(a1)))));
                *(unsigned long long*)(sZ1 + r * WSTRIDE + c0) = z2;
            }
        }
        __syncthreads();

        // ---- phase 3: z2 = lrelu(z1 @ W2^T) via tf32 mma.sync; dv = z2 @ W3^T ----
        {
            const int warp = tid >> 5;
            const int lane = tid & 31;
            const int g  = lane >> 2;
            const int tg = lane & 3;
            const int wr = warp & 3;      // rows wr*32 .. +31
            const int wc = warp >> 2;     // cols wc*32 .. +31

            float c[2][4][4];
            #pragma unroll
            for (int mt = 0; mt < 2; mt++)
                #pragma unroll
                for (int nt = 0; nt < 4; nt++)
                    #pragma unroll
                    for (int q = 0; q < 4; q++) c[mt][nt][q] = 0.0f;

            #pragma unroll 4
            for (int k = 0; k < 128; k += 8) {
                unsigned af[2][4], bf[4][2];
                #pragma unroll
                for (int mt = 0; mt < 2; mt++) {
                    const float* ap = sZ1 + (wr * 32 + mt * 16 + g) * WSTRIDE + k + tg;
                    af[mt][0] = __float_as_uint(ap[0]);
                    af[mt][1] = __float_as_uint(ap[8 * WSTRIDE]);
                    af[mt][2] = __float_as_uint(ap[4]);
                    af[mt][3] = __float_as_uint(ap[8 * WSTRIDE + 4]);
                }
                #pragma unroll
                for (int nt = 0; nt < 4; nt++) {
                    const float* bp = sW2 + (wc * 32 + nt * 8 + g) * WSTRIDE + k + tg;
                    bf[nt][0] = __float_as_uint(bp[0]);
                    bf[nt][1] = __float_as_uint(bp[4]);
                }
                #pragma unroll
                for (int mt = 0; mt < 2; mt++)
                    #pragma unroll
                    for (int nt = 0; nt < 4; nt++)
                        mma_tf32(c[mt][nt], af[mt], bf[nt]);
            }

            float pd[4][6];
            #pragma unroll
            for (int i = 0; i < 4; i++)
                #pragma unroll
                for (int d = 0; d < 6; d++) pd[i][d] = 0.0f;

            #pragma unroll
            for (int nt = 0; nt < 4; nt++) {
                const int col0 = wc * 32 + nt * 8 + 2 * tg;
                #pragma unroll
                for (int d = 0; d < 6; d++) {
                    const float w30 = __ldg(W3 + d * 128 + col0);
                    const float w31 = __ldg(W3 + d * 128 + col0 + 1);
                    #pragma unroll
                    for (int mt = 0; mt < 2; mt++) {
                        pd[mt * 2 + 0][d] += lrelu(c[mt][nt][0]) * w30 + lrelu(c[mt][nt][1]) * w31;
                        pd[mt * 2 + 1][d] += lrelu(c[mt][nt][2]) * w30 + lrelu(c[mt][nt][3]) * w31;
                    }
                }
            }

            #pragma unroll
            for (int m = 1; m < 4; m <<= 1)
                #pragma unroll
                for (int i = 0; i < 4; i++)
                    #pragma unroll
                    for (int d = 0; d < 6; d++)
                        pd[i][d] += __shfl_xor_sync(0xffffffffu, pd[i][d], m);

            if (tg == 0) {
                #pragma unroll
                for (int mt = 0; mt < 2; mt++) {
                    const int r0 = wr * 32 + mt * 16 + g;
                    #pragma unroll
                    for (int d = 0; d < 6; d++) {
                        atomicAdd(sDV + r0 * 6 + d,       pd[mt * 2 + 0][d]);
                        atomicAdd(sDV + (r0 + 8) * 6 + d, pd[mt * 2 + 1][d]);
                    }
                }
            }
        }
        __syncthreads();

        // ---- phase 4: v_next ; phase 5: hN/dv dump ; store prefetched staging ----
        if (tid < RPB) {
            const int r = tid;
            const long long g = rowBase + r;
            const float* se  = sSE + r * 18;
            const float* dvp = sDV + r * 6;

            float w6[6];
            #pragma unroll
            for (int i = 0; i < 6; i++) w6[i] = se[12 + i] + dvp[i];

            const float* Ri = se;
            const float pi0 = se[9], pi1 = se[10], pi2 = se[11];

            const float a0 = Ri[0] * w6[0] + Ri[1] * w6[1] + Ri[2] * w6[2];
            const float a1 = Ri[3] * w6[0] + Ri[4] * w6[1] + Ri[5] * w6[2];
            const float a2 = Ri[6] * w6[0] + Ri[7] * w6[1] + Ri[8] * w6[2];
            const float b0 = Ri[0] * w6[3] + Ri[1] * w6[4] + Ri[2] * w6[5];
            const float b1 = Ri[3] * w6[3] + Ri[4] * w6[4] + Ri[5] * w6[5];
            const float b2 = Ri[6] * w6[3] + Ri[7] * w6[4] + Ri[8] * w6[5];

            float* o = out + g * 18;
            o[12] = a0 + (pi1 * b2 - pi2 * b1);
            o[13] = a1 + (pi2 * b0 - pi0 * b2);
            o[14] = a2 + (pi0 * b1 - pi1 * b0);
            o[15] = b0;
            o[16] = b1;
            o[17] = b2;
        } else {
            const int t = tid - RPB;   // 0..383
            float4* d1 = (float4*)(out + Kll * 18 + rowBase * 12);    // hN: 384 float4
            if (t < 192) {
                float4* d2 = (float4*)(out + Kll * 30 + rowBase * 6); // dv: 192 float4
                d2[t] = ((const float4*)sDV)[t];
            }
            d1[t] = ((const float4*)sH1)[t];
        }
        if (hasNext) {   // staging region free (phase 3 done); consumed by p1 next iter
            ((float4*)(sm + STG_S))[tid] = pf0a;                       // 0..511
            if (tid < 64)  ((float4*)(sm + STG_S))[512 + tid] = pf0b;  // 512..575
            if (tid < 192) ((float4*)(sm + STG_A))[tid]  = pf1;
            if (tid < 384) ((float4*)(sm + STG_H0))[tid] = pf2;
        }
        // loop-top __syncthreads() publishes staging for phase 1
    }
}

extern "C" void kernel_launch(void* const* d_in, const int* in_sizes, int n_in,
                              void* d_out, int out_size)
{
    const float* s   = (const float*)d_in[0];
    const float* a   = (const float*)d_in[1];
    const float* h0  = (const float*)d_in[2];
    const float* Wih = (const float*)d_in[3];
    const float* Whh = (const float*)d_in[4];
    const float* W1  = (const float*)d_in[5];
    const float* W2  = (const float*)d_in[6];
    const float* W3  = (const float*)d_in[7];
    float* out = (float*)d_out;

    const int Krows  = in_sizes[0] / 18;   // s is [K,1,18]
    const int ntiles = Krows / RPB;

    int dev = 0, nsm = 148;
    cudaGetDevice(&dev);
    cudaDeviceGetAttribute(&nsm, cudaDevAttrMultiProcessorCount, dev);
    int nblk = nsm;
    if (nblk > ntiles) nblk = ntiles;

    cudaFuncSetAttribute(auv_step_kernel,
                         cudaFuncAttributeMaxDynamicSharedMemorySize, SMEM_BYTES);
    auv_step_kernel<<<nblk, TPB, SMEM_BYTES>>>(s, a, h0, Wih, Whh, W1, W2, W3, out,
                                               Krows, ntiles);
}

// round 11
// speedup vs baseline: 1.0499x; 1.0499x over previous
#include <cuda_runtime.h>
#include <math.h>

#define RPB 64       // rows per tile
#define TPB 256      // threads per block (8 warps)
#define WSTRIDE 132  // padded stride (floats): conflict-free frag loads

// Shared layout (floats):
#define OFF_W2   0                         // [128][132] = 16896 (tf32 bits, resident)
#define OFF_Z1   (OFF_W2  + 128*WSTRIDE)   // [64][132]  = 8448  (staging overlay, rows<18)
#define OFF_H1   (OFF_Z1  + RPB*WSTRIDE)   // [64][12]   = 768
#define OFF_SE   (OFF_H1  + 768)           // [64][18]   = 1152
#define OFF_DV   (OFF_SE  + 1152)          // [64][6]    = 384
#define OFF_WC   (OFF_DV  + 384)           // [12][40]   = 480 (Wih|Whh fused, zero-padded)
#define SMEM_FLOATS (OFF_WC + 480 + 16)
#define SMEM_BYTES  (SMEM_FLOATS * 4)      // 112,576 B -> 2 CTAs/SM (225.2 KB <= 232 KB)

// staging offsets inside the Z1 region (consumed only by phase 1)
#define STG_S  (OFF_Z1)          // [64][18] = 288 float4
#define STG_A  (OFF_Z1 + 1152)   // [64][6]  = 96 float4
#define STG_H0 (OFF_Z1 + 1536)   // [64][12] = 192 float4

__device__ __forceinline__ float lrelu(float z) { return z >= 0.0f ? z : 0.1f * z; }

__device__ __forceinline__ float fast_tanh(float x) {
    float e = __expf(2.0f * x);
    return 1.0f - __fdividef(2.0f, e + 1.0f);
}

__device__ __forceinline__ unsigned f2tf(float f) {
    unsigned u;
    asm("cvt.rna.tf32.f32 %0, %1;" : "=r"(u) : "f"(f));
    return u;
}

__device__ __forceinline__ unsigned long long ffma2(unsigned long long a,
                                                    unsigned long long b,
                                                    unsigned long long c) {
    unsigned long long d;
    asm("fma.rn.f32x2 %0, %1, %2, %3;" : "=l"(d) : "l"(a), "l"(b), "l"(c));
    return d;
}
__device__ __forceinline__ float unpack_sum(unsigned long long u) {
    float2 f;
    asm("mov.b64 {%0, %1}, %2;" : "=f"(f.x), "=f"(f.y) : "l"(u));
    return f.x + f.y;
}
__device__ __forceinline__ unsigned long long pack2(float lo, float hi) {
    unsigned long long r;
    asm("mov.b64 %0, {%1, %2};" : "=l"(r) : "f"(lo), "f"(hi));
    return r;
}

__device__ __forceinline__ void mma_tf32(float* c, const unsigned* a, const unsigned* b) {
    asm volatile(
        "mma.sync.aligned.m16n8k8.row.col.f32.tf32.tf32.f32 "
        "{%0,%1,%2,%3}, {%4,%5,%6,%7}, {%8,%9}, {%0,%1,%2,%3};"
        : "+f"(c[0]), "+f"(c[1]), "+f"(c[2]), "+f"(c[3])
        : "r"(a[0]), "r"(a[1]), "r"(a[2]), "r"(a[3]), "r"(b[0]), "r"(b[1]));
}

__global__ __launch_bounds__(TPB, 2)
void auv_step_kernel(const float* __restrict__ s,
                     const float* __restrict__ a,
                     const float* __restrict__ h0,
                     const float* __restrict__ Wih,
                     const float* __restrict__ Whh,
                     const float* __restrict__ W1,
                     const float* __restrict__ W2,
                     const float* __restrict__ W3,
                     float* __restrict__ out,
                     int Krows, int ntiles)
{
    extern __shared__ float sm[];
    float* sW2  = sm + OFF_W2;
    float* sZ1  = sm + OFF_Z1;
    float* sH1  = sm + OFF_H1;
    float* sSE  = sm + OFF_SE;
    float* sDV  = sm + OFF_DV;
    float* sWC  = sm + OFF_WC;

    const int tid = threadIdx.x;
    const long long Kll = (long long)Krows;

    // ---- one-time staging: W2 -> tf32 smem; fused RNN weight table ----
    {
        const float4* W2v = (const float4*)W2;
        #pragma unroll
        for (int i = tid; i < 4096; i += TPB) {
            float4 v = W2v[i];
            uint4 t;
            t.x = f2tf(v.x); t.y = f2tf(v.y); t.z = f2tf(v.z); t.w = f2tf(v.w);
            const int row = i >> 5, c4 = i & 31;
            *(uint4*)(sW2 + row * WSTRIDE + c4 * 4) = t;
        }
        // sWC[j][k] = Wih[j][k] (k<21) | Whh[j][k-21] (21<=k<33) | 0
        if (tid < 240) {
            #pragma unroll
            for (int t2 = 0; t2 < 2; t2++) {
                const int i = tid * 2 + t2;
                const int j = i / 40, k = i - j * 40;
                float v = 0.0f;
                if (k < 21) v = Wih[j * 21 + k];
                else if (k < 33) v = Whh[j * 12 + (k - 21)];
                sWC[i] = v;
            }
        }
    }

    // ---- stage first tile directly ----
    {
        const long long rb0 = (long long)blockIdx.x * RPB;
        const float4* sv = (const float4*)(s  + rb0 * 18);
        const float4* av = (const float4*)(a  + rb0 * 6);
        const float4* hv = (const float4*)(h0 + rb0 * 12);
        for (int i = tid; i < 288; i += TPB) ((float4*)(sm + STG_S))[i] = sv[i];
        if (tid < 96)  ((float4*)(sm + STG_A))[tid]  = av[tid];
        if (tid < 192) ((float4*)(sm + STG_H0))[tid] = hv[tid];
    }

    for (int tile = blockIdx.x; tile < ntiles; tile += gridDim.x) {
        const long long rowBase = (long long)tile * RPB;
        __syncthreads();   // staging (initial or from prev iteration) visible

        // ---- phase 1: tid<64 -> SE(3); tid 64..255 -> RNN (3 thr/row, 4 outs) ----
        if (tid < RPB) {
            const int r = tid;
            const long long g = rowBase + r;
            const float* Sr = sm + STG_S + r * 18;

            const float p0 = Sr[0], p1 = Sr[1], p2 = Sr[2];
            float R[9];
            #pragma unroll
            for (int i = 0; i < 9; i++) R[i] = Sr[3 + i];
            float v[6];
            #pragma unroll
            for (int i = 0; i < 6; i++) v[i] = Sr[12 + i];

            const float DT = 0.1f;
            const float rho0 = v[0] * DT, rho1 = v[1] * DT, rho2 = v[2] * DT;
            const float px = v[3] * DT, py = v[4] * DT, pz = v[5] * DT;
            const float th2 = px * px + py * py + pz * pz;
            const bool small = th2 < 1e-8f;
            const float th2s = small ? 1.0f : th2;
            const float th = sqrtf(th2s);
            const float sth = __sinf(th), cth = __cosf(th);
            const float A = small ? (1.0f - th2 * (1.0f / 6.0f))  : __fdividef(sth, th);
            const float B = small ? (0.5f - th2 * (1.0f / 24.0f)) : __fdividef(1.0f - cth, th2s);
            const float C = small ? (1.0f / 6.0f - th2 * (1.0f / 120.0f))
                                  : __fdividef(th - sth, th2s * th);

            const float S[9]  = {0.0f, -pz, py,  pz, 0.0f, -px,  -py, px, 0.0f};
            float S2[9];
            S2[0] = -(py * py + pz * pz); S2[1] = px * py;              S2[2] = px * pz;
            S2[3] = px * py;              S2[4] = -(px * px + pz * pz); S2[5] = py * pz;
            S2[6] = px * pz;              S2[7] = py * pz;              S2[8] = -(px * px + py * py);

            float Re[9], Vm[9];
            #pragma unroll
            for (int i = 0; i < 9; i++) {
                const float I = (i == 0 || i == 4 || i == 8) ? 1.0f : 0.0f;
                Re[i] = I + A * S[i] + B * S2[i];
                Vm[i] = I + B * S[i] + C * S2[i];
            }
            const float pe0 = Vm[0] * rho0 + Vm[1] * rho1 + Vm[2] * rho2;
            const float pe1 = Vm[3] * rho0 + Vm[4] * rho1 + Vm[5] * rho2;
            const float pe2 = Vm[6] * rho0 + Vm[7] * rho1 + Vm[8] * rho2;

            float Rn[9];
            #pragma unroll
            for (int i = 0; i < 3; i++)
                #pragma unroll
                for (int j = 0; j < 3; j++)
                    Rn[i * 3 + j] = R[i * 3 + 0] * Re[0 + j] + R[i * 3 + 1] * Re[3 + j] + R[i * 3 + 2] * Re[6 + j];

            const float pn0 = R[0] * pe0 + R[1] * pe1 + R[2] * pe2 + p0;
            const float pn1 = R[3] * pe0 + R[4] * pe1 + R[5] * pe2 + p1;
            const float pn2 = R[6] * pe0 + R[7] * pe1 + R[8] * pe2 + p2;

            float Ri[9] = {Rn[0], Rn[3], Rn[6], Rn[1], Rn[4], Rn[7], Rn[2], Rn[5], Rn[8]};
            const float pi0 = -(Ri[0] * pn0 + Ri[1] * pn1 + Ri[2] * pn2);
            const float pi1 = -(Ri[3] * pn0 + Ri[4] * pn1 + Ri[5] * pn2);
            const float pi2 = -(Ri[6] * pn0 + Ri[7] * pn1 + Ri[8] * pn2);

            const float u0 = R[0] * v[0] + R[1] * v[1] + R[2] * v[2];
            const float u1 = R[3] * v[0] + R[4] * v[1] + R[5] * v[2];
            const float u2 = R[6] * v[0] + R[7] * v[1] + R[8] * v[2];
            const float w0 = R[0] * v[3] + R[1] * v[4] + R[2] * v[5];
            const float w1 = R[3] * v[3] + R[4] * v[4] + R[5] * v[5];
            const float w2 = R[6] * v[3] + R[7] * v[4] + R[8] * v[5];
            const float t0 = u0 + (p1 * w2 - p2 * w1);
            const float t1 = u1 + (p2 * w0 - p0 * w2);
            const float t2 = u2 + (p0 * w1 - p1 * w0);

            float* se = sSE + r * 18;
            #pragma unroll
            for (int i = 0; i < 9; i++) se[i] = Ri[i];
            se[9]  = pi0; se[10] = pi1; se[11] = pi2;
            se[12] = t0;  se[13] = t1;  se[14] = t2;
            se[15] = w0;  se[16] = w1;  se[17] = w2;

            float* o = out + g * 18;
            o[0] = pn0; o[1] = pn1; o[2] = pn2;
            #pragma unroll
            for (int i = 0; i < 9; i++) o[3 + i] = Rn[i];
        } else {
            const int idx = tid - RPB;            // 0..191
            const int r  = idx / 3;               // row 0..63
            const int j0 = (idx - r * 3) * 4;     // output group: 0,4,8
            const float* Sr  = sm + STG_S  + r * 18;
            const float* Ar  = sm + STG_A  + r * 6;
            const float* H0r = sm + STG_H0 + r * 12;

            // x[0..14]=s[3..17], x[15..20]=a, x[21..32]=h0, x[33..39]=0; packed f32x2
            float x[40];
            #pragma unroll
            for (int i = 0; i < 15; i++) x[i] = Sr[3 + i];
            #pragma unroll
            for (int i = 0; i < 6; i++) x[15 + i] = Ar[i];
            #pragma unroll
            for (int i = 0; i < 12; i++) x[21 + i] = H0r[i];
            #pragma unroll
            for (int i = 33; i < 40; i++) x[i] = 0.0f;
            unsigned long long xp[20];
            #pragma unroll
            for (int i = 0; i < 20; i++) xp[i] = pack2(x[2 * i], x[2 * i + 1]);

            float h4[4];
            #pragma unroll
            for (int jj = 0; jj < 4; jj++) {
                const unsigned long long* wp =
                    (const unsigned long long*)(sWC + (j0 + jj) * 40);
                unsigned long long acc = 0ull;
                #pragma unroll
                for (int q = 0; q < 20; q++) acc = ffma2(xp[q], wp[q], acc);
                h4[jj] = fast_tanh(unpack_sum(acc));
            }
            *(float4*)(sH1 + r * 12 + j0) = make_float4(h4[0], h4[1], h4[2], h4[3]);
        }
        __syncthreads();

        // ---- phase 2: z1 (2 cols x 16 rows/thread) ; prefetch next ; zero sDV ----
        const int tile2 = tile + gridDim.x;
        const bool hasNext = tile2 < ntiles;
        float4 pf0a = make_float4(0.f, 0.f, 0.f, 0.f);
        float4 pf0b = pf0a, pf1 = pf0a, pf2 = pf0a;
        {
            if (hasNext) {
                const long long rb2 = (long long)tile2 * RPB;
                const float4* sv = (const float4*)(s + rb2 * 18);
                pf0a = __ldg(sv + tid);                             // 0..255
                if (tid < 32)  pf0b = __ldg(sv + 256 + tid);        // 256..287
                if (tid < 96)  pf1 = __ldg((const float4*)(a  + rb2 * 6)  + tid);
                if (tid < 192) pf2 = __ldg((const float4*)(h0 + rb2 * 12) + tid);
            }
            if (tid < 96) ((float4*)sDV)[tid] = make_float4(0.f, 0.f, 0.f, 0.f);

            const int c0 = (tid & 63) * 2;        // even col: 0..126
            const int rs = tid >> 6;              // 0..3
            const float4* wa4 = (const float4*)(W1 + c0 * 12);   // cols c0,c0+1: 6 float4
            float4 wv[6];
            #pragma unroll
            for (int q = 0; q < 6; q++) wv[q] = __ldg(wa4 + q);
            unsigned long long w[12];
            #pragma unroll
            for (int q = 0; q < 6; q++) {
                w[2 * q]     = *(unsigned long long*)&wv[q].x;
                w[2 * q + 1] = *(unsigned long long*)&wv[q].z;
            }
            #pragma unroll
            for (int r = rs; r < RPB; r += 4) {
                const unsigned long long* hp = (const unsigned long long*)(sH1 + r * 12);
                unsigned long long h6[6];
                #pragma unroll
                for (int q = 0; q < 6; q++) h6[q] = hp[q];
                unsigned long long a0 = 0ull, a1 = 0ull;
                #pragma unroll
                for (int q = 0; q < 6; q++) {
                    a0 = ffma2(h6[q], w[q], a0);
                    a1 = ffma2(h6[q], w[6 + q], a1);
                }
                const unsigned long long z2 =
                    pack2(__uint_as_float(f2tf(lrelu(unpack_sum(a0)))),
                          __uint_as_float(f2tf(lrelu(unpack_sum(a1)))));
                *(unsigned long long*)(sZ1 + r * WSTRIDE + c0) = z2;
            }
        }
        __syncthreads();

        // ---- phase 3: z2 = lrelu(z1 @ W2^T) via tf32 mma.sync; dv = z2 @ W3^T ----
        {
            const int warp = tid >> 5;
            const int lane = tid & 31;
            const int g  = lane >> 2;
            const int tg = lane & 3;
            const int wr = warp & 1;      // rows wr*32 .. +31
            const int wc = warp >> 1;     // cols wc*32 .. +31

            float c[2][4][4];
            #pragma unroll
            for (int mt = 0; mt < 2; mt++)
                #pragma unroll
                for (int nt = 0; nt < 4; nt++)
                    #pragma unroll
                    for (int q = 0; q < 4; q++) c[mt][nt][q] = 0.0f;

            #pragma unroll 4
            for (int k = 0; k < 128; k += 8) {
                unsigned af[2][4], bf[4][2];
                #pragma unroll
                for (int mt = 0; mt < 2; mt++) {
                    const float* ap = sZ1 + (wr * 32 + mt * 16 + g) * WSTRIDE + k + tg;
                    af[mt][0] = __float_as_uint(ap[0]);
                    af[mt][1] = __float_as_uint(ap[8 * WSTRIDE]);
                    af[mt][2] = __float_as_uint(ap[4]);
                    af[mt][3] = __float_as_uint(ap[8 * WSTRIDE + 4]);
                }
                #pragma unroll
                for (int nt = 0; nt < 4; nt++) {
                    const float* bp = sW2 + (wc * 32 + nt * 8 + g) * WSTRIDE + k + tg;
                    bf[nt][0] = __float_as_uint(bp[0]);
                    bf[nt][1] = __float_as_uint(bp[4]);
                }
                #pragma unroll
                for (int mt = 0; mt < 2; mt++)
                    #pragma unroll
                    for (int nt = 0; nt < 4; nt++)
                        mma_tf32(c[mt][nt], af[mt], bf[nt]);
            }

            float pd[4][6];
            #pragma unroll
            for (int i = 0; i < 4; i++)
                #pragma unroll
                for (int d = 0; d < 6; d++) pd[i][d] = 0.0f;

            #pragma unroll
            for (int nt = 0; nt < 4; nt++) {
                const int col0 = wc * 32 + nt * 8 + 2 * tg;
                #pragma unroll
                for (int d = 0; d < 6; d++) {
                    const float w30 = __ldg(W3 + d * 128 + col0);
                    const float w31 = __ldg(W3 + d * 128 + col0 + 1);
                    #pragma unroll
                    for (int mt = 0; mt < 2; mt++) {
                        pd[mt * 2 + 0][d] += lrelu(c[mt][nt][0]) * w30 + lrelu(c[mt][nt][1]) * w31;
                        pd[mt * 2 + 1][d] += lrelu(c[mt][nt][2]) * w30 + lrelu(c[mt][nt][3]) * w31;
                    }
                }
            }

            #pragma unroll
            for (int m = 1; m < 4; m <<= 1)
                #pragma unroll
                for (int i = 0; i < 4; i++)
                    #pragma unroll
                    for (int d = 0; d < 6; d++)
                        pd[i][d] += __shfl_xor_sync(0xffffffffu, pd[i][d], m);

            if (tg == 0) {
                #pragma unroll
                for (int mt = 0; mt < 2; mt++) {
                    const int r0 = wr * 32 + mt * 16 + g;
                    #pragma unroll
                    for (int d = 0; d < 6; d++) {
                        atomicAdd(sDV + r0 * 6 + d,       pd[mt * 2 + 0][d]);
                        atomicAdd(sDV + (r0 + 8) * 6 + d, pd[mt * 2 + 1][d]);
                    }
                }
            }
        }
        __syncthreads();

        // ---- phase 4: v_next ; phase 5: hN/dv dump ; store prefetched staging ----
        if (tid < RPB) {
            const int r = tid;
            const long long g = rowBase + r;
            const float* se  = sSE + r * 18;
            const float* dvp = sDV + r * 6;

            float w6[6];
            #pragma unroll
            for (int i = 0; i < 6; i++) w6[i] = se[12 + i] + dvp[i];

            const float* Ri = se;
            const float pi0 = se[9], pi1 = se[10], pi2 = se[11];

            const float a0 = Ri[0] * w6[0] + Ri[1] * w6[1] + Ri[2] * w6[2];
            const float a1 = Ri[3] * w6[0] + Ri[4] * w6[1] + Ri[5] * w6[2];
            const float a2 = Ri[6] * w6[0] + Ri[7] * w6[1] + Ri[8] * w6[2];
            const float b0 = Ri[0] * w6[3] + Ri[1] * w6[4] + Ri[2] * w6[5];
            const float b1 = Ri[3] * w6[3] + Ri[4] * w6[4] + Ri[5] * w6[5];
            const float b2 = Ri[6] * w6[3] + Ri[7] * w6[4] + Ri[8] * w6[5];

            float* o = out + g * 18;
            o[12] = a0 + (pi1 * b2 - pi2 * b1);
            o[13] = a1 + (pi2 * b0 - pi0 * b2);
            o[14] = a2 + (pi0 * b1 - pi1 * b0);
            o[15] = b0;
            o[16] = b1;
            o[17] = b2;
        } else {
            const int t = tid - RPB;   // 0..191
            float4* d1 = (float4*)(out + Kll * 18 + rowBase * 12);    // hN: 192 float4
            if (t < 96) {
                float4* d2 = (float4*)(out + Kll * 30 + rowBase * 6); // dv: 96 float4
                d2[t] = ((const float4*)sDV)[t];
            }
            d1[t] = ((const float4*)sH1)[t];
        }
        if (hasNext) {   // staging region free (phase 3 done); consumed by p1 next iter
            ((float4*)(sm + STG_S))[tid] = pf0a;                       // 0..255
            if (tid < 32)  ((float4*)(sm + STG_S))[256 + tid] = pf0b;  // 256..287
            if (tid < 96)  ((float4*)(sm + STG_A))[tid]  = pf1;
            if (tid < 192) ((float4*)(sm + STG_H0))[tid] = pf2;
        }
        // loop-top __syncthreads() publishes staging for phase 1
    }
}

extern "C" void kernel_launch(void* const* d_in, const int* in_sizes, int n_in,
                              void* d_out, int out_size)
{
    const float* s   = (const float*)d_in[0];
    const float* a   = (const float*)d_in[1];
    const float* h0  = (const float*)d_in[2];
    const float* Wih = (const float*)d_in[3];
    const float* Whh = (const float*)d_in[4];
    const float* W1  = (const float*)d_in[5];
    const float* W2  = (const float*)d_in[6];
    const float* W3  = (const float*)d_in[7];
    float* out = (float*)d_out;

    const int Krows  = in_sizes[0] / 18;   // s is [K,1,18]
    const int ntiles = Krows / RPB;

    int dev = 0, nsm = 148;
    cudaGetDevice(&dev);
    cudaDeviceGetAttribute(&nsm, cudaDevAttrMultiProcessorCount, dev);
    int nblk = 2 * nsm;
    if (nblk > ntiles) nblk = ntiles;

    cudaFuncSetAttribute(auv_step_kernel,
                         cudaFuncAttributeMaxDynamicSharedMemorySize, SMEM_BYTES);
    auv_step_kernel<<<nblk, TPB, SMEM_BYTES>>>(s, a, h0, Wih, Whh, W1, W2, W3, out,
                                               Krows, ntiles);
}

// round 13
// speedup vs baseline: 1.2078x; 1.1504x over previous
#include <cuda_runtime.h>
#include <math.h>

#define RPB 64       // rows per tile
#define TPB 256      // threads per block (8 warps)

// Shared layout (floats):
// sW2: fragment-major tf32 W2: word = (k>>3)*1024 + (col>>3)*64 + lane*2 + kh
//      lane = (col&7)*4 + (k&3), kh = (k>>2)&1                      -> 16384 floats
// sA : fragment-major tf32 z1: word = (k>>3)*512 + (r>>4)*128 + lane*4 + slot
//      lane = (r&7)*4 + (k&3), slot = ((r>>3)&1) + 2*((k>>2)&1)     -> 8192 floats
#define OFF_W2   0                         // 16384
#define OFF_A    16384                     // 8192 (staging overlay in first 2304)
#define OFF_H1   (OFF_A  + 8192)           // 768
#define OFF_SE   (OFF_H1 + 768)            // 1152
#define OFF_DV   (OFF_SE + 1152)           // 384
#define OFF_WIH  (OFF_DV + 384)            // 252 pad 256
#define OFF_WHH  (OFF_WIH + 256)           // 144
#define SMEM_FLOATS (OFF_WHH + 144 + 16)
#define SMEM_BYTES  (SMEM_FLOATS * 4)      // 109,184 B -> 2 CTAs/SM (218.4 KB)

// staging offsets inside the sA region (consumed only by phase 1)
#define STG_S  (OFF_A)           // [64][18] = 288 float4
#define STG_A_ (OFF_A + 1152)    // [64][6]  = 96 float4
#define STG_H0 (OFF_A + 1536)    // [64][12] = 192 float4

__device__ __forceinline__ float lrelu(float z) { return z >= 0.0f ? z : 0.1f * z; }

__device__ __forceinline__ float fast_tanh(float x) {
    float e = __expf(2.0f * x);
    return 1.0f - __fdividef(2.0f, e + 1.0f);
}

__device__ __forceinline__ unsigned f2tf(float f) {
    unsigned u;
    asm("cvt.rna.tf32.f32 %0, %1;" : "=r"(u) : "f"(f));
    return u;
}

__device__ __forceinline__ unsigned long long ffma2(unsigned long long a,
                                                    unsigned long long b,
                                                    unsigned long long c) {
    unsigned long long d;
    asm("fma.rn.f32x2 %0, %1, %2, %3;" : "=l"(d) : "l"(a), "l"(b), "l"(c));
    return d;
}
__device__ __forceinline__ float unpack_sum(unsigned long long u) {
    float2 f;
    asm("mov.b64 {%0, %1}, %2;" : "=f"(f.x), "=f"(f.y) : "l"(u));
    return f.x + f.y;
}

__device__ __forceinline__ void mma_tf32(float* c, const unsigned* a, const unsigned* b) {
    asm volatile(
        "mma.sync.aligned.m16n8k8.row.col.f32.tf32.tf32.f32 "
        "{%0,%1,%2,%3}, {%4,%5,%6,%7}, {%8,%9}, {%0,%1,%2,%3};"
        : "+f"(c[0]), "+f"(c[1]), "+f"(c[2]), "+f"(c[3])
        : "r"(a[0]), "r"(a[1]), "r"(a[2]), "r"(a[3]), "r"(b[0]), "r"(b[1]));
}

__global__ __launch_bounds__(TPB, 2)
void auv_step_kernel(const float* __restrict__ s,
                     const float* __restrict__ a,
                     const float* __restrict__ h0,
                     const float* __restrict__ Wih,
                     const float* __restrict__ Whh,
                     const float* __restrict__ W1,
                     const float* __restrict__ W2,
                     const float* __restrict__ W3,
                     float* __restrict__ out,
                     int Krows, int ntiles)
{
    extern __shared__ float sm[];
    float* sW2  = sm + OFF_W2;
    float* sA   = sm + OFF_A;
    float* sH1  = sm + OFF_H1;
    float* sSE  = sm + OFF_SE;
    float* sDV  = sm + OFF_DV;
    float* sWih = sm + OFF_WIH;
    float* sWhh = sm + OFF_WHH;

    const int tid = threadIdx.x;
    const long long Kll = (long long)Krows;

    // ---- one-time staging: W2 -> fragment-major tf32 smem; small weights ----
    {
        for (int i = tid; i < 16384; i += TPB) {
            const int col = i >> 7, k = i & 127;
            const int lane = (col & 7) * 4 + (k & 3);
            const int addr = (k >> 3) * 1024 + (col >> 3) * 64 + lane * 2 + ((k >> 2) & 1);
            sW2[addr] = __uint_as_float(f2tf(__ldg(W2 + i)));
        }
        if (tid < 63) ((float4*)sWih)[tid] = ((const float4*)Wih)[tid];
        if (tid < 36) ((float4*)sWhh)[tid] = ((const float4*)Whh)[tid];
    }

    // ---- stage first tile directly ----
    {
        const long long rb0 = (long long)blockIdx.x * RPB;
        const float4* sv = (const float4*)(s  + rb0 * 18);
        const float4* av = (const float4*)(a  + rb0 * 6);
        const float4* hv = (const float4*)(h0 + rb0 * 12);
        for (int i = tid; i < 288; i += TPB) ((float4*)(sm + STG_S))[i] = sv[i];
        if (tid < 96)  ((float4*)(sm + STG_A_))[tid] = av[tid];
        if (tid < 192) ((float4*)(sm + STG_H0))[tid] = hv[tid];
    }

    for (int tile = blockIdx.x; tile < ntiles; tile += gridDim.x) {
        const long long rowBase = (long long)tile * RPB;
        __syncthreads();   // staging (initial or from prev iteration) visible

        // ---- phase 1: tid<64 -> SE(3); tid 64..255 -> RNN (3 thr/row, 4 outs) ----
        if (tid < RPB) {
            const int r = tid;
            const long long g = rowBase + r;
            const float* Sr = sm + STG_S + r * 18;

            const float p0 = Sr[0], p1 = Sr[1], p2 = Sr[2];
            float R[9];
            #pragma unroll
            for (int i = 0; i < 9; i++) R[i] = Sr[3 + i];
            float v[6];
            #pragma unroll
            for (int i = 0; i < 6; i++) v[i] = Sr[12 + i];

            const float DT = 0.1f;
            const float rho0 = v[0] * DT, rho1 = v[1] * DT, rho2 = v[2] * DT;
            const float px = v[3] * DT, py = v[4] * DT, pz = v[5] * DT;
            const float th2 = px * px + py * py + pz * pz;
            const bool small = th2 < 1e-8f;
            const float th2s = small ? 1.0f : th2;
            const float th = sqrtf(th2s);
            const float sth = __sinf(th), cth = __cosf(th);
            const float A = small ? (1.0f - th2 * (1.0f / 6.0f))  : __fdividef(sth, th);
            const float B = small ? (0.5f - th2 * (1.0f / 24.0f)) : __fdividef(1.0f - cth, th2s);
            const float C = small ? (1.0f / 6.0f - th2 * (1.0f / 120.0f))
                                  : __fdividef(th - sth, th2s * th);

            const float S[9]  = {0.0f, -pz, py,  pz, 0.0f, -px,  -py, px, 0.0f};
            float S2[9];
            S2[0] = -(py * py + pz * pz); S2[1] = px * py;              S2[2] = px * pz;
            S2[3] = px * py;              S2[4] = -(px * px + pz * pz); S2[5] = py * pz;
            S2[6] = px * pz;              S2[7] = py * pz;              S2[8] = -(px * px + py * py);

            float Re[9], Vm[9];
            #pragma unroll
            for (int i = 0; i < 9; i++) {
                const float I = (i == 0 || i == 4 || i == 8) ? 1.0f : 0.0f;
                Re[i] = I + A * S[i] + B * S2[i];
                Vm[i] = I + B * S[i] + C * S2[i];
            }
            const float pe0 = Vm[0] * rho0 + Vm[1] * rho1 + Vm[2] * rho2;
            const float pe1 = Vm[3] * rho0 + Vm[4] * rho1 + Vm[5] * rho2;
            const float pe2 = Vm[6] * rho0 + Vm[7] * rho1 + Vm[8] * rho2;

            float Rn[9];
            #pragma unroll
            for (int i = 0; i < 3; i++)
                #pragma unroll
                for (int j = 0; j < 3; j++)
                    Rn[i * 3 + j] = R[i * 3 + 0] * Re[0 + j] + R[i * 3 + 1] * Re[3 + j] + R[i * 3 + 2] * Re[6 + j];

            const float pn0 = R[0] * pe0 + R[1] * pe1 + R[2] * pe2 + p0;
            const float pn1 = R[3] * pe0 + R[4] * pe1 + R[5] * pe2 + p1;
            const float pn2 = R[6] * pe0 + R[7] * pe1 + R[8] * pe2 + p2;

            float Ri[9] = {Rn[0], Rn[3], Rn[6], Rn[1], Rn[4], Rn[7], Rn[2], Rn[5], Rn[8]};
            const float pi0 = -(Ri[0] * pn0 + Ri[1] * pn1 + Ri[2] * pn2);
            const float pi1 = -(Ri[3] * pn0 + Ri[4] * pn1 + Ri[5] * pn2);
            const float pi2 = -(Ri[6] * pn0 + Ri[7] * pn1 + Ri[8] * pn2);

            const float u0 = R[0] * v[0] + R[1] * v[1] + R[2] * v[2];
            const float u1 = R[3] * v[0] + R[4] * v[1] + R[5] * v[2];
            const float u2 = R[6] * v[0] + R[7] * v[1] + R[8] * v[2];
            const float w0 = R[0] * v[3] + R[1] * v[4] + R[2] * v[5];
            const float w1 = R[3] * v[3] + R[4] * v[4] + R[5] * v[5];
            const float w2 = R[6] * v[3] + R[7] * v[4] + R[8] * v[5];
            const float t0 = u0 + (p1 * w2 - p2 * w1);
            const float t1 = u1 + (p2 * w0 - p0 * w2);
            const float t2 = u2 + (p0 * w1 - p1 * w0);

            float* se = sSE + r * 18;
            #pragma unroll
            for (int i = 0; i < 9; i++) se[i] = Ri[i];
            se[9]  = pi0; se[10] = pi1; se[11] = pi2;
            se[12] = t0;  se[13] = t1;  se[14] = t2;
            se[15] = w0;  se[16] = w1;  se[17] = w2;

            float* o = out + g * 18;
            o[0] = pn0; o[1] = pn1; o[2] = pn2;
            #pragma unroll
            for (int i = 0; i < 9; i++) o[3 + i] = Rn[i];
        } else {
            const int idx = tid - RPB;            // 0..191
            const int r  = idx / 3;               // row 0..63
            const int j0 = (idx - r * 3) * 4;     // output group: 0,4,8
            const float* Sr  = sm + STG_S  + r * 18;
            const float* Ar  = sm + STG_A_ + r * 6;
            const float* H0r = sm + STG_H0 + r * 12;

            float x[21];
            #pragma unroll
            for (int i = 0; i < 15; i++) x[i] = Sr[3 + i];
            #pragma unroll
            for (int i = 0; i < 6; i++) x[15 + i] = Ar[i];
            float h0r[12];
            #pragma unroll
            for (int i = 0; i < 12; i++) h0r[i] = H0r[i];

            #pragma unroll
            for (int jj = 0; jj < 4; jj++) {
                const int j = j0 + jj;
                float acc = 0.0f;
                #pragma unroll
                for (int i = 0; i < 21; i++) acc += x[i] * sWih[j * 21 + i];
                #pragma unroll
                for (int i = 0; i < 12; i++) acc += h0r[i] * sWhh[j * 12 + i];
                sH1[r * 12 + j] = fast_tanh(acc);
            }
        }
        __syncthreads();

        // ---- phase 2: z1 -> tf32, stored FRAGMENT-MAJOR ; prefetch next ; zero sDV ----
        const int tile2 = tile + gridDim.x;
        const bool hasNext = tile2 < ntiles;
        float4 pf0a = make_float4(0.f, 0.f, 0.f, 0.f);
        float4 pf0b = pf0a, pf1 = pf0a, pf2 = pf0a;
        {
            if (hasNext) {
                const long long rb2 = (long long)tile2 * RPB;
                const float4* sv = (const float4*)(s + rb2 * 18);
                pf0a = __ldg(sv + tid);                             // 0..255
                if (tid < 32)  pf0b = __ldg(sv + 256 + tid);        // 256..287
                if (tid < 96)  pf1 = __ldg((const float4*)(a  + rb2 * 6)  + tid);
                if (tid < 192) pf2 = __ldg((const float4*)(h0 + rb2 * 12) + tid);
            }
            if (tid < 96) ((float4*)sDV)[tid] = make_float4(0.f, 0.f, 0.f, 0.f);

            const int c = tid & 127;
            // fragment-major address pieces for this column (c is the GEMM k-index)
            const int cbase = (c >> 3) * 512 + (c & 3) * 4 + 2 * ((c >> 2) & 1);
            const float4* w1v = (const float4*)(W1 + c * 12);
            float4 wa = __ldg(w1v), wb = __ldg(w1v + 1), wc4 = __ldg(w1v + 2);
            unsigned long long w[6];
            w[0] = *(unsigned long long*)&wa.x;  w[1] = *(unsigned long long*)&wa.z;
            w[2] = *(unsigned long long*)&wb.x;  w[3] = *(unsigned long long*)&wb.z;
            w[4] = *(unsigned long long*)&wc4.x; w[5] = *(unsigned long long*)&wc4.z;
            #pragma unroll
            for (int r = tid >> 7; r < RPB; r += 2) {
                const unsigned long long* hp = (const unsigned long long*)(sH1 + r * 12);
                unsigned long long acc = 0ull;
                #pragma unroll
                for (int j = 0; j < 6; j++) acc = ffma2(hp[j], w[j], acc);
                const int addr = cbase + (r >> 4) * 128 + (r & 7) * 16 + ((r >> 3) & 1);
                sA[addr] = __uint_as_float(f2tf(lrelu(unpack_sum(acc))));
            }
        }
        __syncthreads();

        // ---- phase 3: z2 = lrelu(z1 @ W2^T) via tf32 mma.sync (vector frag loads) ----
        {
            const int warp = tid >> 5;
            const int lane = tid & 31;
            const int g  = lane >> 2;
            const int tg = lane & 3;
            const int wr = warp & 1;      // rows wr*32 .. +31
            const int wc = warp >> 1;     // cols wc*32 .. +31

            float c[2][4][4];
            #pragma unroll
            for (int mt = 0; mt < 2; mt++)
                #pragma unroll
                for (int nt = 0; nt < 4; nt++)
                    #pragma unroll
                    for (int q = 0; q < 4; q++) c[mt][nt][q] = 0.0f;

            const uint4* A4 = (const uint4*)sA;   // word/4: chunk*128 + rb*32 + lane
            const uint2* B2 = (const uint2*)sW2;  // word/2: chunk*512 + cb*32 + lane

            #pragma unroll 4
            for (int chunk = 0; chunk < 16; chunk++) {
                unsigned af[2][4], bf[4][2];
                #pragma unroll
                for (int mt = 0; mt < 2; mt++) {
                    const uint4 av = A4[chunk * 128 + (wr * 2 + mt) * 32 + lane];
                    af[mt][0] = av.x; af[mt][1] = av.y; af[mt][2] = av.z; af[mt][3] = av.w;
                }
                #pragma unroll
                for (int nt = 0; nt < 4; nt++) {
                    const uint2 bv = B2[chunk * 512 + (wc * 4 + nt) * 32 + lane];
                    bf[nt][0] = bv.x; bf[nt][1] = bv.y;
                }
                #pragma unroll
                for (int mt = 0; mt < 2; mt++)
                    #pragma unroll
                    for (int nt = 0; nt < 4; nt++)
                        mma_tf32(c[mt][nt], af[mt], bf[nt]);
            }

            float pd[4][6];
            #pragma unroll
            for (int i = 0; i < 4; i++)
                #pragma unroll
                for (int d = 0; d < 6; d++) pd[i][d] = 0.0f;

            #pragma unroll
            for (int nt = 0; nt < 4; nt++) {
                const int col0 = wc * 32 + nt * 8 + 2 * tg;
                #pragma unroll
                for (int d = 0; d < 6; d++) {
                    const float w30 = __ldg(W3 + d * 128 + col0);
                    const float w31 = __ldg(W3 + d * 128 + col0 + 1);
                    #pragma unroll
                    for (int mt = 0; mt < 2; mt++) {
                        pd[mt * 2 + 0][d] += lrelu(c[mt][nt][0]) * w30 + lrelu(c[mt][nt][1]) * w31;
                        pd[mt * 2 + 1][d] += lrelu(c[mt][nt][2]) * w30 + lrelu(c[mt][nt][3]) * w31;
                    }
                }
            }

            #pragma unroll
            for (int m = 1; m < 4; m <<= 1)
                #pragma unroll
                for (int i = 0; i < 4; i++)
                    #pragma unroll
                    for (int d = 0; d < 6; d++)
                        pd[i][d] += __shfl_xor_sync(0xffffffffu, pd[i][d], m);

            if (tg == 0) {
                #pragma unroll
                for (int mt = 0; mt < 2; mt++) {
                    const int r0 = wr * 32 + mt * 16 + g;
                    #pragma unroll
                    for (int d = 0; d < 6; d++) {
                        atomicAdd(sDV + r0 * 6 + d,       pd[mt * 2 + 0][d]);
                        atomicAdd(sDV + (r0 + 8) * 6 + d, pd[mt * 2 + 1][d]);
                    }
                }
            }
        }
        __syncthreads();

        // ---- phase 4: v_next ; phase 5: hN/dv dump ; store prefetched staging ----
        if (tid < RPB) {
            const int r = tid;
            const long long g = rowBase + r;
            const float* se  = sSE + r * 18;
            const float* dvp = sDV + r * 6;

            float w6[6];
            #pragma unroll
            for (int i = 0; i < 6; i++) w6[i] = se[12 + i] + dvp[i];

            const float* Ri = se;
            const float pi0 = se[9], pi1 = se[10], pi2 = se[11];

            const float a0 = Ri[0] * w6[0] + Ri[1] * w6[1] + Ri[2] * w6[2];
            const float a1 = Ri[3] * w6[0] + Ri[4] * w6[1] + Ri[5] * w6[2];
            const float a2 = Ri[6] * w6[0] + Ri[7] * w6[1] + Ri[8] * w6[2];
            const float b0 = Ri[0] * w6[3] + Ri[1] * w6[4] + Ri[2] * w6[5];
            const float b1 = Ri[3] * w6[3] + Ri[4] * w6[4] + Ri[5] * w6[5];
            const float b2 = Ri[6] * w6[3] + Ri[7] * w6[4] + Ri[8] * w6[5];

            float* o = out + g * 18;
            o[12] = a0 + (pi1 * b2 - pi2 * b1);
            o[13] = a1 + (pi2 * b0 - pi0 * b2);
            o[14] = a2 + (pi0 * b1 - pi1 * b0);
            o[15] = b0;
            o[16] = b1;
            o[17] = b2;
        } else {
            const int t = tid - RPB;   // 0..191
            float4* d1 = (float4*)(out + Kll * 18 + rowBase * 12);    // hN: 192 float4
            if (t < 96) {
                float4* d2 = (float4*)(out + Kll * 30 + rowBase * 6); // dv: 96 float4
                d2[t] = ((const float4*)sDV)[t];
            }
            d1[t] = ((const float4*)sH1)[t];
        }
        if (hasNext) {   // staging region free (phase 3 done); consumed by p1 next iter
            ((float4*)(sm + STG_S))[tid] = pf0a;                       // 0..255
            if (tid < 32)  ((float4*)(sm + STG_S))[256 + tid] = pf0b;  // 256..287
            if (tid < 96)  ((float4*)(sm + STG_A_))[tid] = pf1;
            if (tid < 192) ((float4*)(sm + STG_H0))[tid] = pf2;
        }
        // loop-top __syncthreads() publishes staging for phase 1
    }
}

extern "C" void kernel_launch(void* const* d_in, const int* in_sizes, int n_in,
                              void* d_out, int out_size)
{
    const float* s   = (const float*)d_in[0];
    const float* a   = (const float*)d_in[1];
    const float* h0  = (const float*)d_in[2];
    const float* Wih = (const float*)d_in[3];
    const float* Whh = (const float*)d_in[4];
    const float* W1  = (const float*)d_in[5];
    const float* W2  = (const float*)d_in[6];
    const float* W3  = (const float*)d_in[7];
    float* out = (float*)d_out;

    const int Krows  = in_sizes[0] / 18;   // s is [K,1,18]
    const int ntiles = Krows / RPB;

    int dev = 0, nsm = 148;
    cudaGetDevice(&dev);
    cudaDeviceGetAttribute(&nsm, cudaDevAttrMultiProcessorCount, dev);
    int nblk = 2 * nsm;
    if (nblk > ntiles) nblk = ntiles;

    cudaFuncSetAttribute(auv_step_kernel,
                         cudaFuncAttributeMaxDynamicSharedMemorySize, SMEM_BYTES);
    auv_step_kernel<<<nblk, TPB, SMEM_BYTES>>>(s, a, h0, Wih, Whh, W1, W2, W3, out,
                                               Krows, ntiles);
}

// round 15
// speedup vs baseline: 1.2201x; 1.0101x over previous
#include <cuda_runtime.h>
#include <math.h>

#define RPB 64       // rows per tile
#define TPB 256      // threads per block (8 warps)

// Shared layout (floats):
// sW2: fragment-major tf32 W2: word = (k>>3)*1024 + (col>>3)*64 + lane*2 + kh
//      lane = (col&7)*4 + (k&3), kh = (k>>2)&1                      -> 16384 floats
// sA : fragment-major tf32 z1: word = (k>>3)*512 + (r>>4)*128 + lane*4 + slot
//      lane = (r&7)*4 + (k&3), slot = ((r>>3)&1) + 2*((k>>2)&1)     -> 8192 floats
#define OFF_W2   0                         // 16384
#define OFF_A    16384                     // 8192 (staging overlay in first 2304)
#define OFF_H1   (OFF_A  + 8192)           // 768
#define OFF_SE   (OFF_H1 + 768)            // 1152
#define OFF_DV   (OFF_SE + 1152)           // 384
#define OFF_WIH  (OFF_DV + 384)            // 252 pad 256
#define OFF_WHH  (OFF_WIH + 256)           // 144
#define SMEM_FLOATS (OFF_WHH + 144 + 16)
#define SMEM_BYTES  (SMEM_FLOATS * 4)      // 109,184 B -> 2 CTAs/SM (218.4 KB)

// staging offsets inside the sA region (consumed only by phase 1)
#define STG_S  (OFF_A)           // [64][18] = 288 float4
#define STG_A_ (OFF_A + 1152)    // [64][6]  = 96 float4
#define STG_H0 (OFF_A + 1536)    // [64][12] = 192 float4

__device__ __forceinline__ float lrelu(float z) { return z >= 0.0f ? z : 0.1f * z; }

__device__ __forceinline__ float fast_tanh(float x) {
    float e = __expf(2.0f * x);
    return 1.0f - __fdividef(2.0f, e + 1.0f);
}

__device__ __forceinline__ unsigned f2tf(float f) {
    unsigned u;
    asm("cvt.rna.tf32.f32 %0, %1;" : "=r"(u) : "f"(f));
    return u;
}

__device__ __forceinline__ unsigned long long ffma2(unsigned long long a,
                                                    unsigned long long b,
                                                    unsigned long long c) {
    unsigned long long d;
    asm("fma.rn.f32x2 %0, %1, %2, %3;" : "=l"(d) : "l"(a), "l"(b), "l"(c));
    return d;
}
__device__ __forceinline__ float unpack_sum(unsigned long long u) {
    float2 f;
    asm("mov.b64 {%0, %1}, %2;" : "=f"(f.x), "=f"(f.y) : "l"(u));
    return f.x + f.y;
}

__device__ __forceinline__ void mma_tf32(float* c, const unsigned* a, const unsigned* b) {
    asm volatile(
        "mma.sync.aligned.m16n8k8.row.col.f32.tf32.tf32.f32 "
        "{%0,%1,%2,%3}, {%4,%5,%6,%7}, {%8,%9}, {%0,%1,%2,%3};"
        : "+f"(c[0]), "+f"(c[1]), "+f"(c[2]), "+f"(c[3])
        : "r"(a[0]), "r"(a[1]), "r"(a[2]), "r"(a[3]), "r"(b[0]), "r"(b[1]));
}

__global__ __launch_bounds__(TPB, 2)
void auv_step_kernel(const float* __restrict__ s,
                     const float* __restrict__ a,
                     const float* __restrict__ h0,
                     const float* __restrict__ Wih,
                     const float* __restrict__ Whh,
                     const float* __restrict__ W1,
                     const float* __restrict__ W2,
                     const float* __restrict__ W3,
                     float* __restrict__ out,
                     int Krows, int ntiles)
{
    extern __shared__ float sm[];
    float* sW2  = sm + OFF_W2;
    float* sA   = sm + OFF_A;
    float* sH1  = sm + OFF_H1;
    float* sSE  = sm + OFF_SE;
    float* sDV  = sm + OFF_DV;
    float* sWih = sm + OFF_WIH;
    float* sWhh = sm + OFF_WHH;

    const int tid = threadIdx.x;
    const long long Kll = (long long)Krows;

    // ---- one-time staging: W2 -> fragment-major tf32 smem; small weights ----
    {
        for (int i = tid; i < 16384; i += TPB) {
            const int col = i >> 7, k = i & 127;
            const int lane = (col & 7) * 4 + (k & 3);
            const int addr = (k >> 3) * 1024 + (col >> 3) * 64 + lane * 2 + ((k >> 2) & 1);
            sW2[addr] = __uint_as_float(f2tf(__ldg(W2 + i)));
        }
        if (tid < 63) ((float4*)sWih)[tid] = ((const float4*)Wih)[tid];
        if (tid < 36) ((float4*)sWhh)[tid] = ((const float4*)Whh)[tid];
    }

    // ---- stage first tile directly ----
    {
        const long long rb0 = (long long)blockIdx.x * RPB;
        const float4* sv = (const float4*)(s  + rb0 * 18);
        const float4* av = (const float4*)(a  + rb0 * 6);
        const float4* hv = (const float4*)(h0 + rb0 * 12);
        for (int i = tid; i < 288; i += TPB) ((float4*)(sm + STG_S))[i] = sv[i];
        if (tid < 96)  ((float4*)(sm + STG_A_))[tid] = av[tid];
        if (tid < 192) ((float4*)(sm + STG_H0))[tid] = hv[tid];
    }

    for (int tile = blockIdx.x; tile < ntiles; tile += gridDim.x) {
        const long long rowBase = (long long)tile * RPB;
        __syncthreads();   // staging (initial or from prev iteration) visible

        // ---- phase 1: tid<64 -> SE(3); tid 64..255 -> RNN (3 thr/row, 4 outs) ----
        if (tid < RPB) {
            const int r = tid;
            const long long g = rowBase + r;
            const float* Sr = sm + STG_S + r * 18;

            const float p0 = Sr[0], p1 = Sr[1], p2 = Sr[2];
            float R[9];
            #pragma unroll
            for (int i = 0; i < 9; i++) R[i] = Sr[3 + i];
            float v[6];
            #pragma unroll
            for (int i = 0; i < 6; i++) v[i] = Sr[12 + i];

            const float DT = 0.1f;
            const float rho0 = v[0] * DT, rho1 = v[1] * DT, rho2 = v[2] * DT;
            const float px = v[3] * DT, py = v[4] * DT, pz = v[5] * DT;
            const float th2 = px * px + py * py + pz * pz;
            const bool small = th2 < 1e-8f;
            const float th2s = small ? 1.0f : th2;
            const float th = sqrtf(th2s);
            const float sth = __sinf(th), cth = __cosf(th);
            const float A = small ? (1.0f - th2 * (1.0f / 6.0f))  : __fdividef(sth, th);
            const float B = small ? (0.5f - th2 * (1.0f / 24.0f)) : __fdividef(1.0f - cth, th2s);
            const float C = small ? (1.0f / 6.0f - th2 * (1.0f / 120.0f))
                                  : __fdividef(th - sth, th2s * th);

            const float S[9]  = {0.0f, -pz, py,  pz, 0.0f, -px,  -py, px, 0.0f};
            float S2[9];
            S2[0] = -(py * py + pz * pz); S2[1] = px * py;              S2[2] = px * pz;
            S2[3] = px * py;              S2[4] = -(px * px + pz * pz); S2[5] = py * pz;
            S2[6] = px * pz;              S2[7] = py * pz;              S2[8] = -(px * px + py * py);

            float Re[9], Vm[9];
            #pragma unroll
            for (int i = 0; i < 9; i++) {
                const float I = (i == 0 || i == 4 || i == 8) ? 1.0f : 0.0f;
                Re[i] = I + A * S[i] + B * S2[i];
                Vm[i] = I + B * S[i] + C * S2[i];
            }
            const float pe0 = Vm[0] * rho0 + Vm[1] * rho1 + Vm[2] * rho2;
            const float pe1 = Vm[3] * rho0 + Vm[4] * rho1 + Vm[5] * rho2;
            const float pe2 = Vm[6] * rho0 + Vm[7] * rho1 + Vm[8] * rho2;

            float Rn[9];
            #pragma unroll
            for (int i = 0; i < 3; i++)
                #pragma unroll
                for (int j = 0; j < 3; j++)
                    Rn[i * 3 + j] = R[i * 3 + 0] * Re[0 + j] + R[i * 3 + 1] * Re[3 + j] + R[i * 3 + 2] * Re[6 + j];

            const float pn0 = R[0] * pe0 + R[1] * pe1 + R[2] * pe2 + p0;
            const float pn1 = R[3] * pe0 + R[4] * pe1 + R[5] * pe2 + p1;
            const float pn2 = R[6] * pe0 + R[7] * pe1 + R[8] * pe2 + p2;

            float Ri[9] = {Rn[0], Rn[3], Rn[6], Rn[1], Rn[4], Rn[7], Rn[2], Rn[5], Rn[8]};
            const float pi0 = -(Ri[0] * pn0 + Ri[1] * pn1 + Ri[2] * pn2);
            const float pi1 = -(Ri[3] * pn0 + Ri[4] * pn1 + Ri[5] * pn2);
            const float pi2 = -(Ri[6] * pn0 + Ri[7] * pn1 + Ri[8] * pn2);

            const float u0 = R[0] * v[0] + R[1] * v[1] + R[2] * v[2];
            const float u1 = R[3] * v[0] + R[4] * v[1] + R[5] * v[2];
            const float u2 = R[6] * v[0] + R[7] * v[1] + R[8] * v[2];
            const float w0 = R[0] * v[3] + R[1] * v[4] + R[2] * v[5];
            const float w1 = R[3] * v[3] + R[4] * v[4] + R[5] * v[5];
            const float w2 = R[6] * v[3] + R[7] * v[4] + R[8] * v[5];
            const float t0 = u0 + (p1 * w2 - p2 * w1);
            const float t1 = u1 + (p2 * w0 - p0 * w2);
            const float t2 = u2 + (p0 * w1 - p1 * w0);

            float* se = sSE + r * 18;
            #pragma unroll
            for (int i = 0; i < 9; i++) se[i] = Ri[i];
            se[9]  = pi0; se[10] = pi1; se[11] = pi2;
            se[12] = t0;  se[13] = t1;  se[14] = t2;
            se[15] = w0;  se[16] = w1;  se[17] = w2;

            float* o = out + g * 18;
            o[0] = pn0; o[1] = pn1; o[2] = pn2;
            #pragma unroll
            for (int i = 0; i < 9; i++) o[3 + i] = Rn[i];
        } else {
            const int idx = tid - RPB;            // 0..191
            const int r  = idx / 3;               // row 0..63
            const int j0 = (idx - r * 3) * 4;     // output group: 0,4,8
            const float* Sr  = sm + STG_S  + r * 18;
            const float* Ar  = sm + STG_A_ + r * 6;
            const float* H0r = sm + STG_H0 + r * 12;

            // vectorized loads (same values/order as scalar version)
            float x[21];
            x[0] = Sr[3];
            #pragma unroll
            for (int m = 0; m < 7; m++) {               // Sr[4..17], 8B-aligned pairs
                const float2 p = *(const float2*)(Sr + 4 + 2 * m);
                x[1 + 2 * m] = p.x;
                x[2 + 2 * m] = p.y;
            }
            #pragma unroll
            for (int m = 0; m < 3; m++) {               // Ar[0..5], 8B-aligned pairs
                const float2 p = *(const float2*)(Ar + 2 * m);
                x[15 + 2 * m] = p.x;
                x[16 + 2 * m] = p.y;
            }
            float h0r[12];
            #pragma unroll
            for (int m = 0; m < 3; m++) {               // H0r, 16B-aligned quads
                const float4 p = *(const float4*)(H0r + 4 * m);
                h0r[4 * m + 0] = p.x; h0r[4 * m + 1] = p.y;
                h0r[4 * m + 2] = p.z; h0r[4 * m + 3] = p.w;
            }

            #pragma unroll
            for (int jj = 0; jj < 4; jj++) {
                const int j = j0 + jj;
                float acc = 0.0f;
                #pragma unroll
                for (int i = 0; i < 21; i++) acc += x[i] * sWih[j * 21 + i];
                #pragma unroll
                for (int i = 0; i < 12; i++) acc += h0r[i] * sWhh[j * 12 + i];
                sH1[r * 12 + j] = fast_tanh(acc);
            }
        }
        __syncthreads();

        // ---- phase 2: z1 -> tf32, stored FRAGMENT-MAJOR ; prefetch next ; zero sDV ----
        const int tile2 = tile + gridDim.x;
        const bool hasNext = tile2 < ntiles;
        float4 pf0a = make_float4(0.f, 0.f, 0.f, 0.f);
        float4 pf0b = pf0a, pf1 = pf0a, pf2 = pf0a;
        {
            if (hasNext) {
                const long long rb2 = (long long)tile2 * RPB;
                const float4* sv = (const float4*)(s + rb2 * 18);
                pf0a = __ldg(sv + tid);                             // 0..255
                if (tid < 32)  pf0b = __ldg(sv + 256 + tid);        // 256..287
                if (tid < 96)  pf1 = __ldg((const float4*)(a  + rb2 * 6)  + tid);
                if (tid < 192) pf2 = __ldg((const float4*)(h0 + rb2 * 12) + tid);
            }
            if (tid < 96) ((float4*)sDV)[tid] = make_float4(0.f, 0.f, 0.f, 0.f);

            const int c = tid & 127;
            // fragment-major address pieces for this column (c is the GEMM k-index)
            const int cbase = (c >> 3) * 512 + (c & 3) * 4 + 2 * ((c >> 2) & 1);
            const float4* w1v = (const float4*)(W1 + c * 12);
            float4 wa = __ldg(w1v), wb = __ldg(w1v + 1), wc4 = __ldg(w1v + 2);
            unsigned long long w[6];
            w[0] = *(unsigned long long*)&wa.x;  w[1] = *(unsigned long long*)&wa.z;
            w[2] = *(unsigned long long*)&wb.x;  w[3] = *(unsigned long long*)&wb.z;
            w[4] = *(unsigned long long*)&wc4.x; w[5] = *(unsigned long long*)&wc4.z;
            #pragma unroll
            for (int r = tid >> 7; r < RPB; r += 2) {
                // h1 row: 12 floats, 16B-aligned -> 3x LDS.128; halves are the f32x2 pairs
                const float4* hp4 = (const float4*)(sH1 + r * 12);
                float4 ha = hp4[0], hb = hp4[1], hc = hp4[2];
                unsigned long long acc = 0ull;
                acc = ffma2(*(unsigned long long*)&ha.x, w[0], acc);
                acc = ffma2(*(unsigned long long*)&ha.z, w[1], acc);
                acc = ffma2(*(unsigned long long*)&hb.x, w[2], acc);
                acc = ffma2(*(unsigned long long*)&hb.z, w[3], acc);
                acc = ffma2(*(unsigned long long*)&hc.x, w[4], acc);
                acc = ffma2(*(unsigned long long*)&hc.z, w[5], acc);
                const int addr = cbase + (r >> 4) * 128 + (r & 7) * 16 + ((r >> 3) & 1);
                sA[addr] = __uint_as_float(f2tf(lrelu(unpack_sum(acc))));
            }
        }
        __syncthreads();

        // ---- phase 3: z2 = lrelu(z1 @ W2^T) via tf32 mma.sync (vector frag loads) ----
        {
            const int warp = tid >> 5;
            const int lane = tid & 31;
            const int g  = lane >> 2;
            const int tg = lane & 3;
            const int wr = warp & 1;      // rows wr*32 .. +31
            const int wc = warp >> 1;     // cols wc*32 .. +31

            float c[2][4][4];
            #pragma unroll
            for (int mt = 0; mt < 2; mt++)
                #pragma unroll
                for (int nt = 0; nt < 4; nt++)
                    #pragma unroll
                    for (int q = 0; q < 4; q++) c[mt][nt][q] = 0.0f;

            const uint4* A4 = (const uint4*)sA;   // word/4: chunk*128 + rb*32 + lane
            const uint2* B2 = (const uint2*)sW2;  // word/2: chunk*512 + cb*32 + lane

            #pragma unroll 4
            for (int chunk = 0; chunk < 16; chunk++) {
                unsigned af[2][4], bf[4][2];
                #pragma unroll
                for (int mt = 0; mt < 2; mt++) {
                    const uint4 av = A4[chunk * 128 + (wr * 2 + mt) * 32 + lane];
                    af[mt][0] = av.x; af[mt][1] = av.y; af[mt][2] = av.z; af[mt][3] = av.w;
                }
                #pragma unroll
                for (int nt = 0; nt < 4; nt++) {
                    const uint2 bv = B2[chunk * 512 + (wc * 4 + nt) * 32 + lane];
                    bf[nt][0] = bv.x; bf[nt][1] = bv.y;
                }
                #pragma unroll
                for (int mt = 0; mt < 2; mt++)
                    #pragma unroll
                    for (int nt = 0; nt < 4; nt++)
                        mma_tf32(c[mt][nt], af[mt], bf[nt]);
            }

            float pd[4][6];
            #pragma unroll
            for (int i = 0; i < 4; i++)
                #pragma unroll
                for (int d = 0; d < 6; d++) pd[i][d] = 0.0f;

            #pragma unroll
            for (int nt = 0; nt < 4; nt++) {
                const int col0 = wc * 32 + nt * 8 + 2 * tg;
                #pragma unroll
                for (int d = 0; d < 6; d++) {
                    const float w30 = __ldg(W3 + d * 128 + col0);
                    const float w31 = __ldg(W3 + d * 128 + col0 + 1);
                    #pragma unroll
                    for (int mt = 0; mt < 2; mt++) {
                        pd[mt * 2 + 0][d] += lrelu(c[mt][nt][0]) * w30 + lrelu(c[mt][nt][1]) * w31;
                        pd[mt * 2 + 1][d] += lrelu(c[mt][nt][2]) * w30 + lrelu(c[mt][nt][3]) * w31;
                    }
                }
            }

            #pragma unroll
            for (int m = 1; m < 4; m <<= 1)
                #pragma unroll
                for (int i = 0; i < 4; i++)
                    #pragma unroll
                    for (int d = 0; d < 6; d++)
                        pd[i][d] += __shfl_xor_sync(0xffffffffu, pd[i][d], m);

            if (tg == 0) {
                #pragma unroll
                for (int mt = 0; mt < 2; mt++) {
                    const int r0 = wr * 32 + mt * 16 + g;
                    #pragma unroll
                    for (int d = 0; d < 6; d++) {
                        atomicAdd(sDV + r0 * 6 + d,       pd[mt * 2 + 0][d]);
                        atomicAdd(sDV + (r0 + 8) * 6 + d, pd[mt * 2 + 1][d]);
                    }
                }
            }
        }
        __syncthreads();

        // ---- phase 4: v_next ; phase 5: hN/dv dump ; store prefetched staging ----
        if (tid < RPB) {
            const int r = tid;
            const long long g = rowBase + r;
            const float* se  = sSE + r * 18;
            const float* dvp = sDV + r * 6;

            float w6[6];
            #pragma unroll
            for (int i = 0; i < 6; i++) w6[i] = se[12 + i] + dvp[i];

            const float* Ri = se;
            const float pi0 = se[9], pi1 = se[10], pi2 = se[11];

            const float a0 = Ri[0] * w6[0] + Ri[1] * w6[1] + Ri[2] * w6[2];
            const float a1 = Ri[3] * w6[0] + Ri[4] * w6[1] + Ri[5] * w6[2];
            const float a2 = Ri[6] * w6[0] + Ri[7] * w6[1] + Ri[8] * w6[2];
            const float b0 = Ri[0] * w6[3] + Ri[1] * w6[4] + Ri[2] * w6[5];
            const float b1 = Ri[3] * w6[3] + Ri[4] * w6[4] + Ri[5] * w6[5];
            const float b2 = Ri[6] * w6[3] + Ri[7] * w6[4] + Ri[8] * w6[5];

            float* o = out + g * 18;
            o[12] = a0 + (pi1 * b2 - pi2 * b1);
            o[13] = a1 + (pi2 * b0 - pi0 * b2);
            o[14] = a2 + (pi0 * b1 - pi1 * b0);
            o[15] = b0;
            o[16] = b1;
            o[17] = b2;
        } else {
            const int t = tid - RPB;   // 0..191
            float4* d1 = (float4*)(out + Kll * 18 + rowBase * 12);    // hN: 192 float4
            if (t < 96) {
                float4* d2 = (float4*)(out + Kll * 30 + rowBase * 6); // dv: 96 float4
                d2[t] = ((const float4*)sDV)[t];
            }
            d1[t] = ((const float4*)sH1)[t];
        }
        if (hasNext) {   // staging region free (phase 3 done); consumed by p1 next iter
            ((float4*)(sm + STG_S))[tid] = pf0a;                       // 0..255
            if (tid < 32)  ((float4*)(sm + STG_S))[256 + tid] = pf0b;  // 256..287
            if (tid < 96)  ((float4*)(sm + STG_A_))[tid] = pf1;
            if (tid < 192) ((float4*)(sm + STG_H0))[tid] = pf2;
        }
        // loop-top __syncthreads() publishes staging for phase 1
    }
}

extern "C" void kernel_launch(void* const* d_in, const int* in_sizes, int n_in,
                              void* d_out, int out_size)
{
    const float* s   = (const float*)d_in[0];
    const float* a   = (const float*)d_in[1];
    const float* h0  = (const float*)d_in[2];
    const float* Wih = (const float*)d_in[3];
    const float* Whh = (const float*)d_in[4];
    const float* W1  = (const float*)d_in[5];
    const float* W2  = (const float*)d_in[6];
    const float* W3  = (const float*)d_in[7];
    float* out = (float*)d_out;

    const int Krows  = in_sizes[0] / 18;   // s is [K,1,18]
    const int ntiles = Krows / RPB;

    int dev = 0, nsm = 148;
    cudaGetDevice(&dev);
    cudaDeviceGetAttribute(&nsm, cudaDevAttrMultiProcessorCount, dev);
    int nblk = 2 * nsm;
    if (nblk > ntiles) nblk = ntiles;

    cudaFuncSetAttribute(auv_step_kernel,
                         cudaFuncAttributeMaxDynamicSharedMemorySize, SMEM_BYTES);
    auv_step_kernel<<<nblk, TPB, SMEM_BYTES>>>(s, a, h0, Wih, Whh, W1, W2, W3, out,
                                               Krows, ntiles);
}

// round 16
// speedup vs baseline: 1.4173x; 1.1617x over previous
#include <cuda_runtime.h>
#include <math.h>

#define RPB 64       // rows per tile
#define TPB 256      // threads per block (8 warps)

// Shared layout (floats):
// sW2: fragment-major tf32 W2 with sigma-permuted n-positions within each 8-col group:
//      position p holds col c where p = ((c&3)<<1)|((c>>2)&1)  (sigma(2t)=t, sigma(2t+1)=t+4)
//      word = (k>>3)*1024 + (col>>3)*64 + lane*2 + kh, lane = p*4 + (k&3), kh=(k>>2)&1
// sA : fragment-major tf32 z1: word = (k>>3)*512 + (r>>4)*128 + lane*4 + slot
//      lane = (r&7)*4 + (k&3), slot = ((r>>3)&1) + 2*((k>>2)&1)
// sW3f: natural-order B-fragments of W3^T (n=8 padded, 16 chunks): 1024 floats
#define OFF_W2   0                         // 16384
#define OFF_A    16384                     // 8192 (staging overlay in first 2304)
#define OFF_H1   (OFF_A  + 8192)           // 768
#define OFF_SE   (OFF_H1 + 768)            // 1152
#define OFF_DV   (OFF_SE + 1152)           // 384
#define OFF_WIH  (OFF_DV + 384)            // 252 pad 256
#define OFF_WHH  (OFF_WIH + 256)           // 144
#define OFF_W3F  (OFF_WHH + 144)           // 1024
#define SMEM_FLOATS (OFF_W3F + 1024 + 16)
#define SMEM_BYTES  (SMEM_FLOATS * 4)      // 113,280 B -> 2 CTAs/SM (226.6 KB)

// staging offsets inside the sA region (consumed only by phase 1)
#define STG_S  (OFF_A)           // [64][18] = 288 float4
#define STG_A_ (OFF_A + 1152)    // [64][6]  = 96 float4
#define STG_H0 (OFF_A + 1536)    // [64][12] = 192 float4

__device__ __forceinline__ float lrelu(float z) { return z >= 0.0f ? z : 0.1f * z; }

__device__ __forceinline__ float fast_tanh(float x) {
    float e = __expf(2.0f * x);
    return 1.0f - __fdividef(2.0f, e + 1.0f);
}

__device__ __forceinline__ unsigned f2tf(float f) {
    unsigned u;
    asm("cvt.rna.tf32.f32 %0, %1;" : "=r"(u) : "f"(f));
    return u;
}

__device__ __forceinline__ unsigned long long ffma2(unsigned long long a,
                                                    unsigned long long b,
                                                    unsigned long long c) {
    unsigned long long d;
    asm("fma.rn.f32x2 %0, %1, %2, %3;" : "=l"(d) : "l"(a), "l"(b), "l"(c));
    return d;
}
__device__ __forceinline__ float unpack_sum(unsigned long long u) {
    float2 f;
    asm("mov.b64 {%0, %1}, %2;" : "=f"(f.x), "=f"(f.y) : "l"(u));
    return f.x + f.y;
}

__device__ __forceinline__ void mma_tf32(float* c, const unsigned* a, const unsigned* b) {
    asm volatile(
        "mma.sync.aligned.m16n8k8.row.col.f32.tf32.tf32.f32 "
        "{%0,%1,%2,%3}, {%4,%5,%6,%7}, {%8,%9}, {%0,%1,%2,%3};"
        : "+f"(c[0]), "+f"(c[1]), "+f"(c[2]), "+f"(c[3])
        : "r"(a[0]), "r"(a[1]), "r"(a[2]), "r"(a[3]), "r"(b[0]), "r"(b[1]));
}

__global__ __launch_bounds__(TPB, 2)
void auv_step_kernel(const float* __restrict__ s,
                     const float* __restrict__ a,
                     const float* __restrict__ h0,
                     const float* __restrict__ Wih,
                     const float* __restrict__ Whh,
                     const float* __restrict__ W1,
                     const float* __restrict__ W2,
                     const float* __restrict__ W3,
                     float* __restrict__ out,
                     int Krows, int ntiles)
{
    extern __shared__ float sm[];
    float* sW2  = sm + OFF_W2;
    float* sA   = sm + OFF_A;
    float* sH1  = sm + OFF_H1;
    float* sSE  = sm + OFF_SE;
    float* sDV  = sm + OFF_DV;
    float* sWih = sm + OFF_WIH;
    float* sWhh = sm + OFF_WHH;
    float* sW3f = sm + OFF_W3F;

    const int tid = threadIdx.x;
    const long long Kll = (long long)Krows;

    // ---- one-time staging: W2 (sigma-permuted frag-major), W3 B-frags, small weights ----
    {
        for (int i = tid; i < 16384; i += TPB) {
            const int col = i >> 7, k = i & 127;
            const int p = ((col & 3) << 1) | ((col >> 2) & 1);     // sigma^-1(col&7)
            const int lane = p * 4 + (k & 3);
            const int addr = (k >> 3) * 1024 + (col >> 3) * 64 + lane * 2 + ((k >> 2) & 1);
            sW2[addr] = __uint_as_float(f2tf(__ldg(W2 + i)));
        }
        // W3 B-fragments: chunk c (8 k-cols), thread lane: n = lane>>2, kq = lane&3
        // word = c*64 + lane*2 + kh holds W3[n][c*8 + kq + 4*kh] (n>=6 -> 0)
        for (int i = tid; i < 1024; i += TPB) {
            const int chunk = i >> 6, rem = i & 63;
            const int lane = rem >> 1, kh = rem & 1;
            const int n = lane >> 2, kq = lane & 3;
            const int k = chunk * 8 + kq + 4 * kh;
            const float v = (n < 6) ? __ldg(W3 + n * 128 + k) : 0.0f;
            sW3f[i] = __uint_as_float(f2tf(v));
        }
        if (tid < 63) ((float4*)sWih)[tid] = ((const float4*)Wih)[tid];
        if (tid < 36) ((float4*)sWhh)[tid] = ((const float4*)Whh)[tid];
    }

    // ---- stage first tile directly ----
    {
        const long long rb0 = (long long)blockIdx.x * RPB;
        const float4* sv = (const float4*)(s  + rb0 * 18);
        const float4* av = (const float4*)(a  + rb0 * 6);
        const float4* hv = (const float4*)(h0 + rb0 * 12);
        for (int i = tid; i < 288; i += TPB) ((float4*)(sm + STG_S))[i] = sv[i];
        if (tid < 96)  ((float4*)(sm + STG_A_))[tid] = av[tid];
        if (tid < 192) ((float4*)(sm + STG_H0))[tid] = hv[tid];
    }

    for (int tile = blockIdx.x; tile < ntiles; tile += gridDim.x) {
        const long long rowBase = (long long)tile * RPB;
        __syncthreads();   // staging (initial or from prev iteration) visible

        // ---- phase 1: tid<64 -> SE(3); tid 64..255 -> RNN (3 thr/row, 4 outs) ----
        if (tid < RPB) {
            const int r = tid;
            const long long g = rowBase + r;
            const float* Sr = sm + STG_S + r * 18;

            const float p0 = Sr[0], p1 = Sr[1], p2 = Sr[2];
            float R[9];
            #pragma unroll
            for (int i = 0; i < 9; i++) R[i] = Sr[3 + i];
            float v[6];
            #pragma unroll
            for (int i = 0; i < 6; i++) v[i] = Sr[12 + i];

            const float DT = 0.1f;
            const float rho0 = v[0] * DT, rho1 = v[1] * DT, rho2 = v[2] * DT;
            const float px = v[3] * DT, py = v[4] * DT, pz = v[5] * DT;
            const float th2 = px * px + py * py + pz * pz;
            const bool small = th2 < 1e-8f;
            const float th2s = small ? 1.0f : th2;
            const float th = sqrtf(th2s);
            const float sth = __sinf(th), cth = __cosf(th);
            const float A = small ? (1.0f - th2 * (1.0f / 6.0f))  : __fdividef(sth, th);
            const float B = small ? (0.5f - th2 * (1.0f / 24.0f)) : __fdividef(1.0f - cth, th2s);
            const float C = small ? (1.0f / 6.0f - th2 * (1.0f / 120.0f))
                                  : __fdividef(th - sth, th2s * th);

            const float S[9]  = {0.0f, -pz, py,  pz, 0.0f, -px,  -py, px, 0.0f};
            float S2[9];
            S2[0] = -(py * py + pz * pz); S2[1] = px * py;              S2[2] = px * pz;
            S2[3] = px * py;              S2[4] = -(px * px + pz * pz); S2[5] = py * pz;
            S2[6] = px * pz;              S2[7] = py * pz;              S2[8] = -(px * px + py * py);

            float Re[9], Vm[9];
            #pragma unroll
            for (int i = 0; i < 9; i++) {
                const float I = (i == 0 || i == 4 || i == 8) ? 1.0f : 0.0f;
                Re[i] = I + A * S[i] + B * S2[i];
                Vm[i] = I + B * S[i] + C * S2[i];
            }
            const float pe0 = Vm[0] * rho0 + Vm[1] * rho1 + Vm[2] * rho2;
            const float pe1 = Vm[3] * rho0 + Vm[4] * rho1 + Vm[5] * rho2;
            const float pe2 = Vm[6] * rho0 + Vm[7] * rho1 + Vm[8] * rho2;

            float Rn[9];
            #pragma unroll
            for (int i = 0; i < 3; i++)
                #pragma unroll
                for (int j = 0; j < 3; j++)
                    Rn[i * 3 + j] = R[i * 3 + 0] * Re[0 + j] + R[i * 3 + 1] * Re[3 + j] + R[i * 3 + 2] * Re[6 + j];

            const float pn0 = R[0] * pe0 + R[1] * pe1 + R[2] * pe2 + p0;
            const float pn1 = R[3] * pe0 + R[4] * pe1 + R[5] * pe2 + p1;
            const float pn2 = R[6] * pe0 + R[7] * pe1 + R[8] * pe2 + p2;

            float Ri[9] = {Rn[0], Rn[3], Rn[6], Rn[1], Rn[4], Rn[7], Rn[2], Rn[5], Rn[8]};
            const float pi0 = -(Ri[0] * pn0 + Ri[1] * pn1 + Ri[2] * pn2);
            const float pi1 = -(Ri[3] * pn0 + Ri[4] * pn1 + Ri[5] * pn2);
            const float pi2 = -(Ri[6] * pn0 + Ri[7] * pn1 + Ri[8] * pn2);

            const float u0 = R[0] * v[0] + R[1] * v[1] + R[2] * v[2];
            const float u1 = R[3] * v[0] + R[4] * v[1] + R[5] * v[2];
            const float u2 = R[6] * v[0] + R[7] * v[1] + R[8] * v[2];
            const float w0 = R[0] * v[3] + R[1] * v[4] + R[2] * v[5];
            const float w1 = R[3] * v[3] + R[4] * v[4] + R[5] * v[5];
            const float w2 = R[6] * v[3] + R[7] * v[4] + R[8] * v[5];
            const float t0 = u0 + (p1 * w2 - p2 * w1);
            const float t1 = u1 + (p2 * w0 - p0 * w2);
            const float t2 = u2 + (p0 * w1 - p1 * w0);

            float* se = sSE + r * 18;
            #pragma unroll
            for (int i = 0; i < 9; i++) se[i] = Ri[i];
            se[9]  = pi0; se[10] = pi1; se[11] = pi2;
            se[12] = t0;  se[13] = t1;  se[14] = t2;
            se[15] = w0;  se[16] = w1;  se[17] = w2;

            float* o = out + g * 18;
            o[0] = pn0; o[1] = pn1; o[2] = pn2;
            #pragma unroll
            for (int i = 0; i < 9; i++) o[3 + i] = Rn[i];
        } else {
            const int idx = tid - RPB;            // 0..191
            const int r  = idx / 3;               // row 0..63
            const int j0 = (idx - r * 3) * 4;     // output group: 0,4,8
            const float* Sr  = sm + STG_S  + r * 18;
            const float* Ar  = sm + STG_A_ + r * 6;
            const float* H0r = sm + STG_H0 + r * 12;

            float x[21];
            x[0] = Sr[3];
            #pragma unroll
            for (int m = 0; m < 7; m++) {
                const float2 p = *(const float2*)(Sr + 4 + 2 * m);
                x[1 + 2 * m] = p.x;
                x[2 + 2 * m] = p.y;
            }
            #pragma unroll
            for (int m = 0; m < 3; m++) {
                const float2 p = *(const float2*)(Ar + 2 * m);
                x[15 + 2 * m] = p.x;
                x[16 + 2 * m] = p.y;
            }
            float h0r[12];
            #pragma unroll
            for (int m = 0; m < 3; m++) {
                const float4 p = *(const float4*)(H0r + 4 * m);
                h0r[4 * m + 0] = p.x; h0r[4 * m + 1] = p.y;
                h0r[4 * m + 2] = p.z; h0r[4 * m + 3] = p.w;
            }

            #pragma unroll
            for (int jj = 0; jj < 4; jj++) {
                const int j = j0 + jj;
                float acc = 0.0f;
                #pragma unroll
                for (int i = 0; i < 21; i++) acc += x[i] * sWih[j * 21 + i];
                #pragma unroll
                for (int i = 0; i < 12; i++) acc += h0r[i] * sWhh[j * 12 + i];
                sH1[r * 12 + j] = fast_tanh(acc);
            }
        }
        __syncthreads();

        // ---- phase 2: z1 -> tf32, stored FRAGMENT-MAJOR ; prefetch next ; zero sDV ----
        const int tile2 = tile + gridDim.x;
        const bool hasNext = tile2 < ntiles;
        float4 pf0a = make_float4(0.f, 0.f, 0.f, 0.f);
        float4 pf0b = pf0a, pf1 = pf0a, pf2 = pf0a;
        {
            if (hasNext) {
                const long long rb2 = (long long)tile2 * RPB;
                const float4* sv = (const float4*)(s + rb2 * 18);
                pf0a = __ldg(sv + tid);                             // 0..255
                if (tid < 32)  pf0b = __ldg(sv + 256 + tid);        // 256..287
                if (tid < 96)  pf1 = __ldg((const float4*)(a  + rb2 * 6)  + tid);
                if (tid < 192) pf2 = __ldg((const float4*)(h0 + rb2 * 12) + tid);
            }
            if (tid < 96) ((float4*)sDV)[tid] = make_float4(0.f, 0.f, 0.f, 0.f);

            const int c = tid & 127;
            const int cbase = (c >> 3) * 512 + (c & 3) * 4 + 2 * ((c >> 2) & 1);
            const float4* w1v = (const float4*)(W1 + c * 12);
            float4 wa = __ldg(w1v), wb = __ldg(w1v + 1), wc4 = __ldg(w1v + 2);
            unsigned long long w[6];
            w[0] = *(unsigned long long*)&wa.x;  w[1] = *(unsigned long long*)&wa.z;
            w[2] = *(unsigned long long*)&wb.x;  w[3] = *(unsigned long long*)&wb.z;
            w[4] = *(unsigned long long*)&wc4.x; w[5] = *(unsigned long long*)&wc4.z;
            #pragma unroll
            for (int r = tid >> 7; r < RPB; r += 2) {
                const float4* hp4 = (const float4*)(sH1 + r * 12);
                float4 ha = hp4[0], hb = hp4[1], hc = hp4[2];
                unsigned long long acc = 0ull;
                acc = ffma2(*(unsigned long long*)&ha.x, w[0], acc);
                acc = ffma2(*(unsigned long long*)&ha.z, w[1], acc);
                acc = ffma2(*(unsigned long long*)&hb.x, w[2], acc);
                acc = ffma2(*(unsigned long long*)&hb.z, w[3], acc);
                acc = ffma2(*(unsigned long long*)&hc.x, w[4], acc);
                acc = ffma2(*(unsigned long long*)&hc.z, w[5], acc);
                const int addr = cbase + (r >> 4) * 128 + (r & 7) * 16 + ((r >> 3) & 1);
                sA[addr] = __uint_as_float(f2tf(lrelu(unpack_sum(acc))));
            }
        }
        __syncthreads();

        // ---- phase 3: z2 MMA (sigma-permuted cols) + dv via second MMA ----
        {
            const int warp = tid >> 5;
            const int lane = tid & 31;
            const int g  = lane >> 2;
            const int tg = lane & 3;
            const int wr = warp & 1;      // rows wr*32 .. +31
            const int wc = warp >> 1;     // col-groups wc*32 .. +31

            float c[2][4][4];
            #pragma unroll
            for (int mt = 0; mt < 2; mt++)
                #pragma unroll
                for (int nt = 0; nt < 4; nt++)
                    #pragma unroll
                    for (int q = 0; q < 4; q++) c[mt][nt][q] = 0.0f;

            const uint4* A4 = (const uint4*)sA;
            const uint2* B2 = (const uint2*)sW2;

            #pragma unroll 4
            for (int chunk = 0; chunk < 16; chunk++) {
                unsigned af[2][4], bf[4][2];
                #pragma unroll
                for (int mt = 0; mt < 2; mt++) {
                    const uint4 av = A4[chunk * 128 + (wr * 2 + mt) * 32 + lane];
                    af[mt][0] = av.x; af[mt][1] = av.y; af[mt][2] = av.z; af[mt][3] = av.w;
                }
                #pragma unroll
                for (int nt = 0; nt < 4; nt++) {
                    const uint2 bv = B2[chunk * 512 + (wc * 4 + nt) * 32 + lane];
                    bf[nt][0] = bv.x; bf[nt][1] = bv.y;
                }
                #pragma unroll
                for (int mt = 0; mt < 2; mt++)
                    #pragma unroll
                    for (int nt = 0; nt < 4; nt++)
                        mma_tf32(c[mt][nt], af[mt], bf[nt]);
            }

            // dv partial over this warp's 32 z2-cols via tf32 MMA:
            // A = lrelu(z2) C-frags (reordered {c0,c2,c1,c3} — valid natural-col A-frag
            // thanks to the sigma-permuted W2 store), B = W3 natural-order fragments.
            float cd[2][4];
            #pragma unroll
            for (int mt = 0; mt < 2; mt++)
                #pragma unroll
                for (int q = 0; q < 4; q++) cd[mt][q] = 0.0f;

            const uint2* W3F2 = (const uint2*)sW3f;
            unsigned bfw[4][2];
            #pragma unroll
            for (int nt = 0; nt < 4; nt++) {
                const uint2 bv = W3F2[(wc * 4 + nt) * 32 + lane];
                bfw[nt][0] = bv.x; bfw[nt][1] = bv.y;
            }
            #pragma unroll
            for (int mt = 0; mt < 2; mt++) {
                #pragma unroll
                for (int nt = 0; nt < 4; nt++) {
                    unsigned av[4];
                    av[0] = f2tf(lrelu(c[mt][nt][0]));
                    av[1] = f2tf(lrelu(c[mt][nt][2]));
                    av[2] = f2tf(lrelu(c[mt][nt][1]));
                    av[3] = f2tf(lrelu(c[mt][nt][3]));
                    mma_tf32(cd[mt], av, bfw[nt]);
                }
            }

            // cross-warp (wc) reduction: direct atomic adds; cols {2tg, 2tg+1}, valid tg<3
            if (tg < 3) {
                #pragma unroll
                for (int mt = 0; mt < 2; mt++) {
                    const int r0 = wr * 32 + mt * 16 + g;
                    atomicAdd(sDV + r0 * 6 + 2 * tg,           cd[mt][0]);
                    atomicAdd(sDV + r0 * 6 + 2 * tg + 1,       cd[mt][1]);
                    atomicAdd(sDV + (r0 + 8) * 6 + 2 * tg,     cd[mt][2]);
                    atomicAdd(sDV + (r0 + 8) * 6 + 2 * tg + 1, cd[mt][3]);
                }
            }
        }
        __syncthreads();

        // ---- phase 4: v_next ; phase 5: hN/dv dump ; store prefetched staging ----
        if (tid < RPB) {
            const int r = tid;
            const long long g = rowBase + r;
            const float* se  = sSE + r * 18;
            const float* dvp = sDV + r * 6;

            float w6[6];
            #pragma unroll
            for (int i = 0; i < 6; i++) w6[i] = se[12 + i] + dvp[i];

            const float* Ri = se;
            const float pi0 = se[9], pi1 = se[10], pi2 = se[11];

            const float a0 = Ri[0] * w6[0] + Ri[1] * w6[1] + Ri[2] * w6[2];
            const float a1 = Ri[3] * w6[0] + Ri[4] * w6[1] + Ri[5] * w6[2];
            const float a2 = Ri[6] * w6[0] + Ri[7] * w6[1] + Ri[8] * w6[2];
            const float b0 = Ri[0] * w6[3] + Ri[1] * w6[4] + Ri[2] * w6[5];
            const float b1 = Ri[3] * w6[3] + Ri[4] * w6[4] + Ri[5] * w6[5];
            const float b2 = Ri[6] * w6[3] + Ri[7] * w6[4] + Ri[8] * w6[5];

            float* o = out + g * 18;
            o[12] = a0 + (pi1 * b2 - pi2 * b1);
            o[13] = a1 + (pi2 * b0 - pi0 * b2);
            o[14] = a2 + (pi0 * b1 - pi1 * b0);
            o[15] = b0;
            o[16] = b1;
            o[17] = b2;
        } else {
            const int t = tid - RPB;   // 0..191
            float4* d1 = (float4*)(out + Kll * 18 + rowBase * 12);    // hN: 192 float4
            if (t < 96) {
                float4* d2 = (float4*)(out + Kll * 30 + rowBase * 6); // dv: 96 float4
                d2[t] = ((const float4*)sDV)[t];
            }
            d1[t] = ((const float4*)sH1)[t];
        }
        if (hasNext) {   // staging region free (phase 3 done); consumed by p1 next iter
            ((float4*)(sm + STG_S))[tid] = pf0a;                       // 0..255
            if (tid < 32)  ((float4*)(sm + STG_S))[256 + tid] = pf0b;  // 256..287
            if (tid < 96)  ((float4*)(sm + STG_A_))[tid] = pf1;
            if (tid < 192) ((float4*)(sm + STG_H0))[tid] = pf2;
        }
        // loop-top __syncthreads() publishes staging for phase 1
    }
}

extern "C" void kernel_launch(void* const* d_in, const int* in_sizes, int n_in,
                              void* d_out, int out_size)
{
    const float* s   = (const float*)d_in[0];
    const float* a   = (const float*)d_in[1];
    const float* h0  = (const float*)d_in[2];
    const float* Wih = (const float*)d_in[3];
    const float* Whh = (const float*)d_in[4];
    const float* W1  = (const float*)d_in[5];
    const float* W2  = (const float*)d_in[6];
    const float* W3  = (const float*)d_in[7];
    float* out = (float*)d_out;

    const int Krows  = in_sizes[0] / 18;   // s is [K,1,18]
    const int ntiles = Krows / RPB;

    int dev = 0, nsm = 148;
    cudaGetDevice(&dev);
    cudaDeviceGetAttribute(&nsm, cudaDevAttrMultiProcessorCount, dev);
    int nblk = 2 * nsm;
    if (nblk > ntiles) nblk = ntiles;

    cudaFuncSetAttribute(auv_step_kernel,
                         cudaFuncAttributeMaxDynamicSharedMemorySize, SMEM_BYTES);
    auv_step_kernel<<<nblk, TPB, SMEM_BYTES>>>(s, a, h0, Wih, Whh, W1, W2, W3, out,
                                               Krows, ntiles);
}

// round 17
// speedup vs baseline: 1.6061x; 1.1332x over previous
#include <cuda_runtime.h>
#include <math.h>

#define RPB 64       // rows per tile
#define TPB 256      // threads per block (8 warps)

// Shared layout (floats):
// sW2 : fragment-major tf32 W2, sigma-permuted n within 8-groups (see R16)
// sA  : fragment-major tf32 z1 (phase-3 A operand), canonical recipe
// sH1F: fragment-major FP32 h1 (phase-2 A operand), same recipe, 64x16 (k 12..15 unused)
// sW3f: natural-order W3^T B-fragments (n=8 padded)
#define OFF_W2   0                         // 16384
#define OFF_A    16384                     // 8192 (staging overlay in first 2304)
#define OFF_H1F  (OFF_A   + 8192)          // 1024
#define OFF_SE   (OFF_H1F + 1024)          // 1152
#define OFF_DV   (OFF_SE  + 1152)          // 384
#define OFF_WIH  (OFF_DV  + 384)           // 252 pad 256
#define OFF_WHH  (OFF_WIH + 256)           // 144
#define OFF_W3F  (OFF_WHH + 144)           // 1024
#define SMEM_FLOATS (OFF_W3F + 1024 + 16)
#define SMEM_BYTES  (SMEM_FLOATS * 4)      // 114,304 B -> 2 CTAs/SM (228.6 KB)

// staging offsets inside the sA region (consumed only by phase 1)
#define STG_S  (OFF_A)           // [64][18] = 288 float4
#define STG_A_ (OFF_A + 1152)    // [64][6]  = 96 float4
#define STG_H0 (OFF_A + 1536)    // [64][12] = 192 float4

__device__ __forceinline__ float lrelu(float z) { return z >= 0.0f ? z : 0.1f * z; }

__device__ __forceinline__ float fast_tanh(float x) {
    float e = __expf(2.0f * x);
    return 1.0f - __fdividef(2.0f, e + 1.0f);
}

__device__ __forceinline__ unsigned f2tf(float f) {
    unsigned u;
    asm("cvt.rna.tf32.f32 %0, %1;" : "=r"(u) : "f"(f));
    return u;
}

__device__ __forceinline__ void mma_tf32(float* c, const unsigned* a, const unsigned* b) {
    asm volatile(
        "mma.sync.aligned.m16n8k8.row.col.f32.tf32.tf32.f32 "
        "{%0,%1,%2,%3}, {%4,%5,%6,%7}, {%8,%9}, {%0,%1,%2,%3};"
        : "+f"(c[0]), "+f"(c[1]), "+f"(c[2]), "+f"(c[3])
        : "r"(a[0]), "r"(a[1]), "r"(a[2]), "r"(a[3]), "r"(b[0]), "r"(b[1]));
}

__global__ __launch_bounds__(TPB, 2)
void auv_step_kernel(const float* __restrict__ s,
                     const float* __restrict__ a,
                     const float* __restrict__ h0,
                     const float* __restrict__ Wih,
                     const float* __restrict__ Whh,
                     const float* __restrict__ W1,
                     const float* __restrict__ W2,
                     const float* __restrict__ W3,
                     float* __restrict__ out,
                     int Krows, int ntiles)
{
    extern __shared__ float sm[];
    float* sW2  = sm + OFF_W2;
    float* sA   = sm + OFF_A;
    float* sH1F = sm + OFF_H1F;
    float* sSE  = sm + OFF_SE;
    float* sDV  = sm + OFF_DV;
    float* sWih = sm + OFF_WIH;
    float* sWhh = sm + OFF_WHH;
    float* sW3f = sm + OFF_W3F;

    const int tid = threadIdx.x;
    const long long Kll = (long long)Krows;

    // ---- one-time staging: W2 (sigma frag-major), W3 B-frags, small weights ----
    {
        for (int i = tid; i < 16384; i += TPB) {
            const int col = i >> 7, k = i & 127;
            const int p = ((col & 3) << 1) | ((col >> 2) & 1);     // sigma^-1(col&7)
            const int lane = p * 4 + (k & 3);
            const int addr = (k >> 3) * 1024 + (col >> 3) * 64 + lane * 2 + ((k >> 2) & 1);
            sW2[addr] = __uint_as_float(f2tf(__ldg(W2 + i)));
        }
        for (int i = tid; i < 1024; i += TPB) {
            const int chunk = i >> 6, rem = i & 63;
            const int lane = rem >> 1, kh = rem & 1;
            const int n = lane >> 2, kq = lane & 3;
            const int k = chunk * 8 + kq + 4 * kh;
            const float v = (n < 6) ? __ldg(W3 + n * 128 + k) : 0.0f;
            sW3f[i] = __uint_as_float(f2tf(v));
        }
        if (tid < 63) ((float4*)sWih)[tid] = ((const float4*)Wih)[tid];
        if (tid < 36) ((float4*)sWhh)[tid] = ((const float4*)Whh)[tid];
    }

    // ---- stage first tile directly ----
    {
        const long long rb0 = (long long)blockIdx.x * RPB;
        const float4* sv = (const float4*)(s  + rb0 * 18);
        const float4* av = (const float4*)(a  + rb0 * 6);
        const float4* hv = (const float4*)(h0 + rb0 * 12);
        for (int i = tid; i < 288; i += TPB) ((float4*)(sm + STG_S))[i] = sv[i];
        if (tid < 96)  ((float4*)(sm + STG_A_))[tid] = av[tid];
        if (tid < 192) ((float4*)(sm + STG_H0))[tid] = hv[tid];
    }

    for (int tile = blockIdx.x; tile < ntiles; tile += gridDim.x) {
        const long long rowBase = (long long)tile * RPB;
        __syncthreads();   // staging visible

        // ---- phase 1: tid<64 -> SE(3); tid 64..255 -> RNN (3 thr/row, 4 outs) ----
        if (tid < RPB) {
            const int r = tid;
            const long long g = rowBase + r;
            const float* Sr = sm + STG_S + r * 18;

            const float p0 = Sr[0], p1 = Sr[1], p2 = Sr[2];
            float R[9];
            #pragma unroll
            for (int i = 0; i < 9; i++) R[i] = Sr[3 + i];
            float v[6];
            #pragma unroll
            for (int i = 0; i < 6; i++) v[i] = Sr[12 + i];

            const float DT = 0.1f;
            const float rho0 = v[0] * DT, rho1 = v[1] * DT, rho2 = v[2] * DT;
            const float px = v[3] * DT, py = v[4] * DT, pz = v[5] * DT;
            const float th2 = px * px + py * py + pz * pz;
            const bool small = th2 < 1e-8f;
            const float th2s = small ? 1.0f : th2;
            const float th = sqrtf(th2s);
            const float sth = __sinf(th), cth = __cosf(th);
            const float A = small ? (1.0f - th2 * (1.0f / 6.0f))  : __fdividef(sth, th);
            const float B = small ? (0.5f - th2 * (1.0f / 24.0f)) : __fdividef(1.0f - cth, th2s);
            const float C = small ? (1.0f / 6.0f - th2 * (1.0f / 120.0f))
                                  : __fdividef(th - sth, th2s * th);

            const float S[9]  = {0.0f, -pz, py,  pz, 0.0f, -px,  -py, px, 0.0f};
            float S2[9];
            S2[0] = -(py * py + pz * pz); S2[1] = px * py;              S2[2] = px * pz;
            S2[3] = px * py;              S2[4] = -(px * px + pz * pz); S2[5] = py * pz;
            S2[6] = px * pz;              S2[7] = py * pz;              S2[8] = -(px * px + py * py);

            float Re[9], Vm[9];
            #pragma unroll
            for (int i = 0; i < 9; i++) {
                const float I = (i == 0 || i == 4 || i == 8) ? 1.0f : 0.0f;
                Re[i] = I + A * S[i] + B * S2[i];
                Vm[i] = I + B * S[i] + C * S2[i];
            }
            const float pe0 = Vm[0] * rho0 + Vm[1] * rho1 + Vm[2] * rho2;
            const float pe1 = Vm[3] * rho0 + Vm[4] * rho1 + Vm[5] * rho2;
            const float pe2 = Vm[6] * rho0 + Vm[7] * rho1 + Vm[8] * rho2;

            float Rn[9];
            #pragma unroll
            for (int i = 0; i < 3; i++)
                #pragma unroll
                for (int j = 0; j < 3; j++)
                    Rn[i * 3 + j] = R[i * 3 + 0] * Re[0 + j] + R[i * 3 + 1] * Re[3 + j] + R[i * 3 + 2] * Re[6 + j];

            const float pn0 = R[0] * pe0 + R[1] * pe1 + R[2] * pe2 + p0;
            const float pn1 = R[3] * pe0 + R[4] * pe1 + R[5] * pe2 + p1;
            const float pn2 = R[6] * pe0 + R[7] * pe1 + R[8] * pe2 + p2;

            float Ri[9] = {Rn[0], Rn[3], Rn[6], Rn[1], Rn[4], Rn[7], Rn[2], Rn[5], Rn[8]};
            const float pi0 = -(Ri[0] * pn0 + Ri[1] * pn1 + Ri[2] * pn2);
            const float pi1 = -(Ri[3] * pn0 + Ri[4] * pn1 + Ri[5] * pn2);
            const float pi2 = -(Ri[6] * pn0 + Ri[7] * pn1 + Ri[8] * pn2);

            const float u0 = R[0] * v[0] + R[1] * v[1] + R[2] * v[2];
            const float u1 = R[3] * v[0] + R[4] * v[1] + R[5] * v[2];
            const float u2 = R[6] * v[0] + R[7] * v[1] + R[8] * v[2];
            const float w0 = R[0] * v[3] + R[1] * v[4] + R[2] * v[5];
            const float w1 = R[3] * v[3] + R[4] * v[4] + R[5] * v[5];
            const float w2 = R[6] * v[3] + R[7] * v[4] + R[8] * v[5];
            const float t0 = u0 + (p1 * w2 - p2 * w1);
            const float t1 = u1 + (p2 * w0 - p0 * w2);
            const float t2 = u2 + (p0 * w1 - p1 * w0);

            float* se = sSE + r * 18;
            #pragma unroll
            for (int i = 0; i < 9; i++) se[i] = Ri[i];
            se[9]  = pi0; se[10] = pi1; se[11] = pi2;
            se[12] = t0;  se[13] = t1;  se[14] = t2;
            se[15] = w0;  se[16] = w1;  se[17] = w2;

            float* o = out + g * 18;
            o[0] = pn0; o[1] = pn1; o[2] = pn2;
            #pragma unroll
            for (int i = 0; i < 9; i++) o[3 + i] = Rn[i];
        } else {
            const int idx = tid - RPB;            // 0..191
            const int r  = idx / 3;               // row 0..63
            const int j0 = (idx - r * 3) * 4;     // output group: 0,4,8
            const float* Sr  = sm + STG_S  + r * 18;
            const float* Ar  = sm + STG_A_ + r * 6;
            const float* H0r = sm + STG_H0 + r * 12;

            float x[21];
            x[0] = Sr[3];
            #pragma unroll
            for (int m = 0; m < 7; m++) {
                const float2 p = *(const float2*)(Sr + 4 + 2 * m);
                x[1 + 2 * m] = p.x;
                x[2 + 2 * m] = p.y;
            }
            #pragma unroll
            for (int m = 0; m < 3; m++) {
                const float2 p = *(const float2*)(Ar + 2 * m);
                x[15 + 2 * m] = p.x;
                x[16 + 2 * m] = p.y;
            }
            float h0r[12];
            #pragma unroll
            for (int m = 0; m < 3; m++) {
                const float4 p = *(const float4*)(H0r + 4 * m);
                h0r[4 * m + 0] = p.x; h0r[4 * m + 1] = p.y;
                h0r[4 * m + 2] = p.z; h0r[4 * m + 3] = p.w;
            }

            float h4[4];
            #pragma unroll
            for (int jj = 0; jj < 4; jj++) {
                const int j = j0 + jj;
                float acc = 0.0f;
                #pragma unroll
                for (int i = 0; i < 21; i++) acc += x[i] * sWih[j * 21 + i];
                #pragma unroll
                for (int i = 0; i < 12; i++) acc += h0r[i] * sWhh[j * 12 + i];
                h4[jj] = fast_tanh(acc);
            }
            // write fp32 h1 into A-fragment-major sH1F:
            // word = (j>>3)*512 + (r>>4)*128 + ((r&7)*4+(j&3))*4 + ((r>>3)&1) + 2*((j>>2)&1)
            const int q   = j0 >> 3;
            const int ofs = ((r >> 3) & 1) + 2 * ((j0 >> 2) & 1);
            float* b = sH1F + q * 512 + (r >> 4) * 128 + (r & 7) * 16 + ofs;
            b[0]  = h4[0];
            b[4]  = h4[1];
            b[8]  = h4[2];
            b[12] = h4[3];
        }
        __syncthreads();

        // ---- phase 2: z1 = lrelu(h1 @ W1^T) via tf32 MMA ; prefetch ; zero sDV ----
        const int tile2 = tile + gridDim.x;
        const bool hasNext = tile2 < ntiles;
        float4 pf0a = make_float4(0.f, 0.f, 0.f, 0.f);
        float4 pf0b = pf0a, pf1 = pf0a, pf2 = pf0a;
        {
            if (hasNext) {
                const long long rb2 = (long long)tile2 * RPB;
                const float4* sv = (const float4*)(s + rb2 * 18);
                pf0a = __ldg(sv + tid);                             // 0..255
                if (tid < 32)  pf0b = __ldg(sv + 256 + tid);        // 256..287
                if (tid < 96)  pf1 = __ldg((const float4*)(a  + rb2 * 6)  + tid);
                if (tid < 192) pf2 = __ldg((const float4*)(h0 + rb2 * 12) + tid);
            }
            if (tid < 96) ((float4*)sDV)[tid] = make_float4(0.f, 0.f, 0.f, 0.f);

            const int warp = tid >> 5;
            const int lane = tid & 31;
            const int g  = lane >> 2;
            const int tg = lane & 3;
            const int rt = warp & 3;      // row-tile (16 rows)
            const int ch = warp >> 2;     // column half (8 groups of 8)

            // A-frags: fp32 from sH1F -> tf32; chunk1 k=12..15 are zero
            const float4 a0v = ((const float4*)sH1F)[rt * 32 + lane];
            const float4 a1v = ((const float4*)sH1F)[128 + rt * 32 + lane];
            unsigned af0[4] = { f2tf(a0v.x), f2tf(a0v.y), f2tf(a0v.z), f2tf(a0v.w) };
            unsigned af1[4] = { f2tf(a1v.x), f2tf(a1v.y), 0u, 0u };

            float c[8][4];
            #pragma unroll
            for (int i = 0; i < 8; i++)
                #pragma unroll
                for (int q = 0; q < 4; q++) c[i][q] = 0.0f;

            #pragma unroll
            for (int cg8 = 0; cg8 < 8; cg8++) {
                const int n = (ch * 8 + cg8) * 8 + g;
                const float* wb = W1 + n * 12;
                unsigned b0[2], b1[2];
                b0[0] = f2tf(__ldg(wb + tg));
                b0[1] = f2tf(__ldg(wb + tg + 4));
                b1[0] = f2tf(__ldg(wb + 8 + tg));
                b1[1] = 0u;                                   // k=12..15 zero
                mma_tf32(c[cg8], af0, b0);
                mma_tf32(c[cg8], af1, b1);
            }

            // store lrelu(c) -> sA fragment-major; (g,g+8) pairs are adjacent words
            const int co0 = ((2 * tg) & 3) * 4 + 2 * ((tg >> 1) & 1);
            const int co1 = ((2 * tg + 1) & 3) * 4 + 2 * ((tg >> 1) & 1);
            #pragma unroll
            for (int cg8 = 0; cg8 < 8; cg8++) {
                const int base = (ch * 8 + cg8) * 512 + rt * 128 + g * 16;
                float2 v0, v1;
                v0.x = __uint_as_float(f2tf(lrelu(c[cg8][0])));
                v0.y = __uint_as_float(f2tf(lrelu(c[cg8][2])));
                v1.x = __uint_as_float(f2tf(lrelu(c[cg8][1])));
                v1.y = __uint_as_float(f2tf(lrelu(c[cg8][3])));
                *(float2*)(sA + base + co0) = v0;
                *(float2*)(sA + base + co1) = v1;
            }
        }
        __syncthreads();

        // ---- phase 3: z2 MMA (sigma-permuted cols) + dv via second MMA ----
        {
            const int warp = tid >> 5;
            const int lane = tid & 31;
            const int g  = lane >> 2;
            const int tg = lane & 3;
            const int wr = warp & 1;      // rows wr*32 .. +31
            const int wc = warp >> 1;     // col-groups wc*32 .. +31

            float c[2][4][4];
            #pragma unroll
            for (int mt = 0; mt < 2; mt++)
                #pragma unroll
                for (int nt = 0; nt < 4; nt++)
                    #pragma unroll
                    for (int q = 0; q < 4; q++) c[mt][nt][q] = 0.0f;

            const uint4* A4 = (const uint4*)sA;
            const uint2* B2 = (const uint2*)sW2;

            #pragma unroll 4
            for (int chunk = 0; chunk < 16; chunk++) {
                unsigned af[2][4], bf[4][2];
                #pragma unroll
                for (int mt = 0; mt < 2; mt++) {
                    const uint4 av = A4[chunk * 128 + (wr * 2 + mt) * 32 + lane];
                    af[mt][0] = av.x; af[mt][1] = av.y; af[mt][2] = av.z; af[mt][3] = av.w;
                }
                #pragma unroll
                for (int nt = 0; nt < 4; nt++) {
                    const uint2 bv = B2[chunk * 512 + (wc * 4 + nt) * 32 + lane];
                    bf[nt][0] = bv.x; bf[nt][1] = bv.y;
                }
                #pragma unroll
                for (int mt = 0; mt < 2; mt++)
                    #pragma unroll
                    for (int nt = 0; nt < 4; nt++)
                        mma_tf32(c[mt][nt], af[mt], bf[nt]);
            }

            // dv via second MMA: C-frags reordered {c0,c2,c1,c3} (sigma trick), W3 B-frags
            float cd[2][4];
            #pragma unroll
            for (int mt = 0; mt < 2; mt++)
                #pragma unroll
                for (int q = 0; q < 4; q++) cd[mt][q] = 0.0f;

            const uint2* W3F2 = (const uint2*)sW3f;
            unsigned bfw[4][2];
            #pragma unroll
            for (int nt = 0; nt < 4; nt++) {
                const uint2 bv = W3F2[(wc * 4 + nt) * 32 + lane];
                bfw[nt][0] = bv.x; bfw[nt][1] = bv.y;
            }
            #pragma unroll
            for (int mt = 0; mt < 2; mt++) {
                #pragma unroll
                for (int nt = 0; nt < 4; nt++) {
                    unsigned av[4];
                    av[0] = f2tf(lrelu(c[mt][nt][0]));
                    av[1] = f2tf(lrelu(c[mt][nt][2]));
                    av[2] = f2tf(lrelu(c[mt][nt][1]));
                    av[3] = f2tf(lrelu(c[mt][nt][3]));
                    mma_tf32(cd[mt], av, bfw[nt]);
                }
            }

            if (tg < 3) {
                #pragma unroll
                for (int mt = 0; mt < 2; mt++) {
                    const int r0 = wr * 32 + mt * 16 + g;
                    atomicAdd(sDV + r0 * 6 + 2 * tg,           cd[mt][0]);
                    atomicAdd(sDV + r0 * 6 + 2 * tg + 1,       cd[mt][1]);
                    atomicAdd(sDV + (r0 + 8) * 6 + 2 * tg,     cd[mt][2]);
                    atomicAdd(sDV + (r0 + 8) * 6 + 2 * tg + 1, cd[mt][3]);
                }
            }
        }
        __syncthreads();

        // ---- phase 4: v_next ; phase 5: hN/dv dump ; store prefetched staging ----
        if (tid < RPB) {
            const int r = tid;
            const long long g = rowBase + r;
            const float* se  = sSE + r * 18;
            const float* dvp = sDV + r * 6;

            float w6[6];
            #pragma unroll
            for (int i = 0; i < 6; i++) w6[i] = se[12 + i] + dvp[i];

            const float* Ri = se;
            const float pi0 = se[9], pi1 = se[10], pi2 = se[11];

            const float a0 = Ri[0] * w6[0] + Ri[1] * w6[1] + Ri[2] * w6[2];
            const float a1 = Ri[3] * w6[0] + Ri[4] * w6[1] + Ri[5] * w6[2];
            const float a2 = Ri[6] * w6[0] + Ri[7] * w6[1] + Ri[8] * w6[2];
            const float b0 = Ri[0] * w6[3] + Ri[1] * w6[4] + Ri[2] * w6[5];
            const float b1 = Ri[3] * w6[3] + Ri[4] * w6[4] + Ri[5] * w6[5];
            const float b2 = Ri[6] * w6[3] + Ri[7] * w6[4] + Ri[8] * w6[5];

            float* o = out + g * 18;
            o[12] = a0 + (pi1 * b2 - pi2 * b1);
            o[13] = a1 + (pi2 * b0 - pi0 * b2);
            o[14] = a2 + (pi0 * b1 - pi1 * b0);
            o[15] = b0;
            o[16] = b1;
            o[17] = b2;
        } else {
            const int t = tid - RPB;   // 0..191
            float4* d1 = (float4*)(out + Kll * 18 + rowBase * 12);    // hN: 192 float4
            if (t < 96) {
                float4* d2 = (float4*)(out + Kll * 30 + rowBase * 6); // dv: 96 float4
                d2[t] = ((const float4*)sDV)[t];
            }
            // hN quad (r, j0..j0+3) gathered from fragment-major sH1F (exact fp32)
            const int r  = t / 3;
            const int j0 = (t - r * 3) * 4;
            const int q   = j0 >> 3;
            const int ofs = ((r >> 3) & 1) + 2 * ((j0 >> 2) & 1);
            const float* b = sH1F + q * 512 + (r >> 4) * 128 + (r & 7) * 16 + ofs;
            d1[t] = make_float4(b[0], b[4], b[8], b[12]);
        }
        if (hasNext) {   // staging region free (phase 3 done); consumed by p1 next iter
            ((float4*)(sm + STG_S))[tid] = pf0a;                       // 0..255
            if (tid < 32)  ((float4*)(sm + STG_S))[256 + tid] = pf0b;  // 256..287
            if (tid < 96)  ((float4*)(sm + STG_A_))[tid] = pf1;
            if (tid < 192) ((float4*)(sm + STG_H0))[tid] = pf2;
        }
        // loop-top __syncthreads() publishes staging for phase 1
    }
}

extern "C" void kernel_launch(void* const* d_in, const int* in_sizes, int n_in,
                              void* d_out, int out_size)
{
    const float* s   = (const float*)d_in[0];
    const float* a   = (const float*)d_in[1];
    const float* h0  = (const float*)d_in[2];
    const float* Wih = (const float*)d_in[3];
    const float* Whh = (const float*)d_in[4];
    const float* W1  = (const float*)d_in[5];
    const float* W2  = (const float*)d_in[6];
    const float* W3  = (const float*)d_in[7];
    float* out = (float*)d_out;

    const int Krows  = in_sizes[0] / 18;   // s is [K,1,18]
    const int ntiles = Krows / RPB;

    int dev = 0, nsm = 148;
    cudaGetDevice(&dev);
    cudaDeviceGetAttribute(&nsm, cudaDevAttrMultiProcessorCount, dev);
    int nblk = 2 * nsm;
    if (nblk > ntiles) nblk = ntiles;

    cudaFuncSetAttribute(auv_step_kernel,
                         cudaFuncAttributeMaxDynamicSharedMemorySize, SMEM_BYTES);
    auv_step_kernel<<<nblk, TPB, SMEM_BYTES>>>(s, a, h0, Wih, Whh, W1, W2, W3, out,
                                               Krows, ntiles);
}